// round 1
// baseline (speedup 1.0000x reference)
#include <cuda_runtime.h>
#include <math.h>

// Problem constants
#define BATCH 4
#define TSEQ  2048
#define EDIM  1024
#define FDIM  4096
#define NHEAD 16
#define HS    64
#define BT    (BATCH*TSEQ)   // 8192 rows

// ---------------- scratch (no allocation allowed) ----------------
__device__ float g_h [BT*(size_t)EDIM];
__device__ float g_q [BT*(size_t)EDIM];
__device__ float g_k [BT*(size_t)EDIM];
__device__ float g_v [BT*(size_t)EDIM];
__device__ float g_y [BT*(size_t)EDIM];
__device__ float g_x2[BT*(size_t)EDIM];
__device__ float g_h2[BT*(size_t)EDIM];
__device__ float g_ff[BT*(size_t)FDIM];

// ---------------- LayerNorm (weight only, eps=1e-5) ----------------
// one block per row, 256 threads, 4 floats per thread
__global__ void __launch_bounds__(256) ln_kernel(const float* __restrict__ x,
                                                 const float* __restrict__ w,
                                                 float* __restrict__ out)
{
    const int row = blockIdx.x;
    const int tid = threadIdx.x;
    const float4 xv = reinterpret_cast<const float4*>(x + (size_t)row * EDIM)[tid];
    float s  = xv.x + xv.y + xv.z + xv.w;
    float s2 = xv.x*xv.x + xv.y*xv.y + xv.z*xv.z + xv.w*xv.w;
    #pragma unroll
    for (int off = 16; off; off >>= 1) {
        s  += __shfl_xor_sync(0xffffffffu, s,  off);
        s2 += __shfl_xor_sync(0xffffffffu, s2, off);
    }
    __shared__ float sh[16];
    const int warp = tid >> 5, lane = tid & 31;
    if (lane == 0) { sh[warp] = s; sh[warp + 8] = s2; }
    __syncthreads();
    s = 0.f; s2 = 0.f;
    #pragma unroll
    for (int i = 0; i < 8; i++) { s += sh[i]; s2 += sh[i + 8]; }
    const float mu  = s * (1.0f / EDIM);
    const float var = s2 * (1.0f / EDIM) - mu * mu;
    const float inv = rsqrtf(var + 1e-5f);
    const float4 wv = reinterpret_cast<const float4*>(w)[tid];
    float4 o;
    o.x = (xv.x - mu) * inv * wv.x;
    o.y = (xv.y - mu) * inv * wv.y;
    o.z = (xv.z - mu) * inv * wv.z;
    o.w = (xv.w - mu) * inv * wv.w;
    reinterpret_cast<float4*>(out + (size_t)row * EDIM)[tid] = o;
}

// ---------------- SGEMM: C[M,N] = A[M,K] @ B[K,N] (+bias)(+res)(relu) ----------------
// 128x128 tile, BK=8, 256 threads, 8x8 per thread. All dims divisible by tile sizes.
template<int BIAS, int RES, int RELU>
__global__ void __launch_bounds__(256) sgemm_kernel(
    const float* __restrict__ A, const float* __restrict__ B,
    const float* __restrict__ bias, const float* __restrict__ res,
    float* __restrict__ C, int M, int N, int K)
{
    __shared__ float As[8][128];
    __shared__ float Bs[8][128];

    const int tid = threadIdx.x;
    const int bx = blockIdx.x, by = blockIdx.y;
    const int tx = tid & 15, ty = tid >> 4;

    float acc[8][8];
    #pragma unroll
    for (int i = 0; i < 8; i++)
        #pragma unroll
        for (int j = 0; j < 8; j++) acc[i][j] = 0.f;

    // A tile loader: row = tid/2 (0..127), k-quad = (tid&1)*4
    const int arow  = tid >> 1;
    const int acol4 = (tid & 1) << 2;
    const float* Aptr = A + (size_t)(by * 128 + arow) * K + acol4;
    // B tile loader: k-row = tid/32 (0..7), col = (tid&31)*4
    const int brow = tid >> 5;
    const int bcol = (tid & 31) << 2;
    const float* Bptr = B + (size_t)brow * N + bx * 128 + bcol;

    for (int k0 = 0; k0 < K; k0 += 8) {
        const float4 av = *reinterpret_cast<const float4*>(Aptr); Aptr += 8;
        const float4 bv = *reinterpret_cast<const float4*>(Bptr); Bptr += (size_t)8 * N;
        As[acol4 + 0][arow] = av.x;
        As[acol4 + 1][arow] = av.y;
        As[acol4 + 2][arow] = av.z;
        As[acol4 + 3][arow] = av.w;
        *reinterpret_cast<float4*>(&Bs[brow][bcol]) = bv;
        __syncthreads();

        #pragma unroll
        for (int kk = 0; kk < 8; kk++) {
            float a[8], b[8];
            *reinterpret_cast<float4*>(a)     = *reinterpret_cast<const float4*>(&As[kk][ty * 8]);
            *reinterpret_cast<float4*>(a + 4) = *reinterpret_cast<const float4*>(&As[kk][ty * 8 + 4]);
            *reinterpret_cast<float4*>(b)     = *reinterpret_cast<const float4*>(&Bs[kk][tx * 8]);
            *reinterpret_cast<float4*>(b + 4) = *reinterpret_cast<const float4*>(&Bs[kk][tx * 8 + 4]);
            #pragma unroll
            for (int i = 0; i < 8; i++)
                #pragma unroll
                for (int j = 0; j < 8; j++)
                    acc[i][j] = fmaf(a[i], b[j], acc[i][j]);
        }
        __syncthreads();
    }

    const int crow0 = by * 128 + ty * 8;
    const int ccol0 = bx * 128 + tx * 8;
    #pragma unroll
    for (int i = 0; i < 8; i++) {
        const size_t rbase = (size_t)(crow0 + i) * N;
        #pragma unroll
        for (int j4 = 0; j4 < 8; j4 += 4) {
            const int col = ccol0 + j4;
            float4 o;
            o.x = acc[i][j4 + 0]; o.y = acc[i][j4 + 1];
            o.z = acc[i][j4 + 2]; o.w = acc[i][j4 + 3];
            if (BIAS) {
                const float4 bv = *reinterpret_cast<const float4*>(bias + col);
                o.x += bv.x; o.y += bv.y; o.z += bv.z; o.w += bv.w;
            }
            if (RES) {
                const float4 rv = *reinterpret_cast<const float4*>(res + rbase + col);
                o.x += rv.x; o.y += rv.y; o.z += rv.z; o.w += rv.w;
            }
            if (RELU) {
                o.x = fmaxf(o.x, 0.f); o.y = fmaxf(o.y, 0.f);
                o.z = fmaxf(o.z, 0.f); o.w = fmaxf(o.w, 0.f);
            }
            *reinterpret_cast<float4*>(C + rbase + col) = o;
        }
    }
}

// ---------------- Causal flash attention, fp32, 64x64 tiles ----------------
// grid (T/64, H, B), 256 threads. q/k/v/y layout: [B*T, E] with head h at cols h*HS..h*HS+63
#define SM_LD 65  // padded row stride in shared
__global__ void __launch_bounds__(256) attn_kernel(
    const float* __restrict__ Q, const float* __restrict__ K,
    const float* __restrict__ V, float* __restrict__ Y)
{
    extern __shared__ float smem[];
    float* Qs = smem;                 // 64 x 65
    float* Ks = Qs + 64 * SM_LD;      // 64 x 65
    float* Vs = Ks + 64 * SM_LD;      // 64 x 65
    float* Ps = Vs + 64 * SM_LD;      // 64 x 65

    const int qt = blockIdx.x, h = blockIdx.y, b = blockIdx.z;
    const int tid = threadIdx.x;
    const int c0 = (tid & 15) << 2;   // 4-col group (key idx or head dim)
    const int r0 = (tid >> 4) << 2;   // 4-row group (query idx)
    const float scale = 0.03125f;     // E^-0.5 = 1/32

    // Load Q tile (pre-scaled)
    for (int i = tid; i < 64 * 16; i += 256) {
        const int r = i >> 4, d4 = (i & 15) << 2;
        const float4 qv = *reinterpret_cast<const float4*>(
            Q + ((size_t)(b * TSEQ + qt * 64 + r)) * EDIM + h * HS + d4);
        Qs[r * SM_LD + d4 + 0] = qv.x * scale;
        Qs[r * SM_LD + d4 + 1] = qv.y * scale;
        Qs[r * SM_LD + d4 + 2] = qv.z * scale;
        Qs[r * SM_LD + d4 + 3] = qv.w * scale;
    }

    float m_i[4], l_i[4], o[4][4];
    #pragma unroll
    for (int i = 0; i < 4; i++) {
        m_i[i] = -1e30f; l_i[i] = 0.f;
        #pragma unroll
        for (int j = 0; j < 4; j++) o[i][j] = 0.f;
    }
    __syncthreads();

    for (int kt = 0; kt <= qt; kt++) {
        // Load K, V tiles
        for (int i = tid; i < 64 * 16; i += 256) {
            const int r = i >> 4, d4 = (i & 15) << 2;
            const size_t gbase = ((size_t)(b * TSEQ + kt * 64 + r)) * EDIM + h * HS + d4;
            const float4 kv = *reinterpret_cast<const float4*>(K + gbase);
            const float4 vv = *reinterpret_cast<const float4*>(V + gbase);
            Ks[r * SM_LD + d4 + 0] = kv.x; Ks[r * SM_LD + d4 + 1] = kv.y;
            Ks[r * SM_LD + d4 + 2] = kv.z; Ks[r * SM_LD + d4 + 3] = kv.w;
            Vs[r * SM_LD + d4 + 0] = vv.x; Vs[r * SM_LD + d4 + 1] = vv.y;
            Vs[r * SM_LD + d4 + 2] = vv.z; Vs[r * SM_LD + d4 + 3] = vv.w;
        }
        __syncthreads();

        // S = Qs @ Ks^T   (4x4 per thread)
        float s4[4][4];
        #pragma unroll
        for (int i = 0; i < 4; i++)
            #pragma unroll
            for (int j = 0; j < 4; j++) s4[i][j] = 0.f;
        #pragma unroll 8
        for (int d = 0; d < 64; d++) {
            float qr[4], kc[4];
            #pragma unroll
            for (int i = 0; i < 4; i++) qr[i] = Qs[(r0 + i) * SM_LD + d];
            #pragma unroll
            for (int j = 0; j < 4; j++) kc[j] = Ks[(c0 + j) * SM_LD + d];
            #pragma unroll
            for (int i = 0; i < 4; i++)
                #pragma unroll
                for (int j = 0; j < 4; j++)
                    s4[i][j] = fmaf(qr[i], kc[j], s4[i][j]);
        }

        // causal mask on the diagonal tile
        if (kt == qt) {
            #pragma unroll
            for (int i = 0; i < 4; i++)
                #pragma unroll
                for (int j = 0; j < 4; j++)
                    if (c0 + j > r0 + i) s4[i][j] = -1e30f;
        }

        // row-max across the 16 lanes sharing these rows
        float mx[4];
        #pragma unroll
        for (int i = 0; i < 4; i++) {
            float v = fmaxf(fmaxf(s4[i][0], s4[i][1]), fmaxf(s4[i][2], s4[i][3]));
            #pragma unroll
            for (int off = 8; off; off >>= 1)
                v = fmaxf(v, __shfl_xor_sync(0xffffffffu, v, off, 16));
            mx[i] = v;
        }

        float alpha[4], rs[4];
        #pragma unroll
        for (int i = 0; i < 4; i++) {
            const float m_new = fmaxf(m_i[i], mx[i]);
            alpha[i] = __expf(m_i[i] - m_new);
            m_i[i] = m_new;
            float r = 0.f;
            #pragma unroll
            for (int j = 0; j < 4; j++) {
                const float p = __expf(s4[i][j] - m_new);
                s4[i][j] = p;
                r += p;
            }
            #pragma unroll
            for (int off = 8; off; off >>= 1)
                r += __shfl_xor_sync(0xffffffffu, r, off, 16);
            rs[i] = r;
            l_i[i] = l_i[i] * alpha[i] + r;
        }

        // store P to shared; rescale O
        #pragma unroll
        for (int i = 0; i < 4; i++) {
            #pragma unroll
            for (int j = 0; j < 4; j++) {
                Ps[(r0 + i) * SM_LD + c0 + j] = s4[i][j];
                o[i][j] *= alpha[i];
            }
        }
        __syncthreads();

        // O += P @ V   (rows r0.., dim cols c0..)
        #pragma unroll 8
        for (int k = 0; k < 64; k++) {
            float pr[4], vc[4];
            #pragma unroll
            for (int i = 0; i < 4; i++) pr[i] = Ps[(r0 + i) * SM_LD + k];
            #pragma unroll
            for (int j = 0; j < 4; j++) vc[j] = Vs[k * SM_LD + c0 + j];
            #pragma unroll
            for (int i = 0; i < 4; i++)
                #pragma unroll
                for (int j = 0; j < 4; j++)
                    o[i][j] = fmaf(pr[i], vc[j], o[i][j]);
        }
        __syncthreads();
    }

    // write Y
    #pragma unroll
    for (int i = 0; i < 4; i++) {
        const float inv = 1.0f / l_i[i];
        float4 ov;
        ov.x = o[i][0] * inv; ov.y = o[i][1] * inv;
        ov.z = o[i][2] * inv; ov.w = o[i][3] * inv;
        *reinterpret_cast<float4*>(
            Y + ((size_t)(b * TSEQ + qt * 64 + r0 + i)) * EDIM + h * HS + c0) = ov;
    }
}

// ---------------- launch ----------------
extern "C" void kernel_launch(void* const* d_in, const int* in_sizes, int n_in,
                              void* d_out, int out_size)
{
    const float* x    = (const float*)d_in[0];
    const float* Wq   = (const float*)d_in[1];
    const float* Wk   = (const float*)d_in[2];
    const float* Wv   = (const float*)d_in[3];
    const float* Wo   = (const float*)d_in[4];
    const float* bo   = (const float*)d_in[5];
    const float* ln1w = (const float*)d_in[6];
    const float* ln2w = (const float*)d_in[7];
    const float* W1   = (const float*)d_in[8];
    const float* b1   = (const float*)d_in[9];
    const float* W2   = (const float*)d_in[10];
    const float* b2   = (const float*)d_in[11];
    float* out = (float*)d_out;

    float *h, *q, *k, *v, *y, *x2, *h2, *ff;
    cudaGetSymbolAddress((void**)&h,  g_h);
    cudaGetSymbolAddress((void**)&q,  g_q);
    cudaGetSymbolAddress((void**)&k,  g_k);
    cudaGetSymbolAddress((void**)&v,  g_v);
    cudaGetSymbolAddress((void**)&y,  g_y);
    cudaGetSymbolAddress((void**)&x2, g_x2);
    cudaGetSymbolAddress((void**)&h2, g_h2);
    cudaGetSymbolAddress((void**)&ff, g_ff);

    const int smem_attn = 4 * 64 * SM_LD * (int)sizeof(float);
    cudaFuncSetAttribute(attn_kernel, cudaFuncAttributeMaxDynamicSharedMemorySize, smem_attn);

    // 1) LN1
    ln_kernel<<<BT, 256>>>(x, ln1w, h);

    // 2-4) QKV projections
    dim3 gE(EDIM / 128, BT / 128);
    sgemm_kernel<0,0,0><<<gE, 256>>>(h, Wq, nullptr, nullptr, q, BT, EDIM, EDIM);
    sgemm_kernel<0,0,0><<<gE, 256>>>(h, Wk, nullptr, nullptr, k, BT, EDIM, EDIM);
    sgemm_kernel<0,0,0><<<gE, 256>>>(h, Wv, nullptr, nullptr, v, BT, EDIM, EDIM);

    // 5) causal attention
    attn_kernel<<<dim3(TSEQ / 64, NHEAD, BATCH), 256, smem_attn>>>(q, k, v, y);

    // 6) out projection + bias + residual(x)
    sgemm_kernel<1,1,0><<<gE, 256>>>(y, Wo, bo, x, x2, BT, EDIM, EDIM);

    // 7) LN2
    ln_kernel<<<BT, 256>>>(x2, ln2w, h2);

    // 8) FFN up + relu
    dim3 gF(FDIM / 128, BT / 128);
    sgemm_kernel<1,0,1><<<gF, 256>>>(h2, W1, b1, nullptr, ff, BT, FDIM, EDIM);

    // 9) FFN down + bias + residual(x2) -> out
    sgemm_kernel<1,1,0><<<gE, 256>>>(ff, W2, b2, x2, out, BT, EDIM, FDIM);
}

// round 3
// speedup vs baseline: 2.2067x; 2.2067x over previous
#include <cuda_runtime.h>
#include <cstdint>
#include <math.h>

// Problem constants
#define BATCH 4
#define TSEQ  2048
#define EDIM  1024
#define FDIM  4096
#define NHEAD 16
#define HS    64
#define BT    (BATCH*TSEQ)   // 8192 rows

// ---------------- scratch (no allocation allowed) ----------------
__device__ float g_h [BT*(size_t)EDIM];
__device__ float g_q [BT*(size_t)EDIM];
__device__ float g_k [BT*(size_t)EDIM];
__device__ float g_v [BT*(size_t)EDIM];
__device__ float g_y [BT*(size_t)EDIM];
__device__ float g_x2[BT*(size_t)EDIM];
__device__ float g_h2[BT*(size_t)EDIM];
__device__ float g_ff[BT*(size_t)FDIM];
// tf32-rounded weight copies
__device__ float g_wq[EDIM*(size_t)EDIM];
__device__ float g_wk[EDIM*(size_t)EDIM];
__device__ float g_wv[EDIM*(size_t)EDIM];
__device__ float g_wo[EDIM*(size_t)EDIM];
__device__ float g_w1[EDIM*(size_t)FDIM];
__device__ float g_w2[FDIM*(size_t)EDIM];

// ---------------- helpers ----------------
// cvt.rna.tf32.f32 requires a .b32 destination register
__device__ __forceinline__ float tf32r(float x) {
    uint32_t r;
    asm("cvt.rna.tf32.f32 %0, %1;" : "=r"(r) : "f"(x));
    return __uint_as_float(r);
}

#define CP_ASYNC16(dst, src) \
    asm volatile("cp.async.cg.shared.global [%0], [%1], 16;\n" :: "r"(dst), "l"(src))
#define CP_COMMIT() asm volatile("cp.async.commit_group;\n" ::)
#define CP_WAIT1()  asm volatile("cp.async.wait_group 1;\n" ::)
#define CP_WAIT0()  asm volatile("cp.async.wait_group 0;\n" ::)

// ---------------- weight pre-round (fp32 -> tf32-rounded fp32) ----------------
__global__ void __launch_bounds__(256) round_kernel(const float* __restrict__ in,
                                                    float* __restrict__ out, int n4)
{
    const float4* in4 = reinterpret_cast<const float4*>(in);
    float4* out4 = reinterpret_cast<float4*>(out);
    for (int i = blockIdx.x * blockDim.x + threadIdx.x; i < n4; i += gridDim.x * blockDim.x) {
        float4 v = in4[i];
        v.x = tf32r(v.x); v.y = tf32r(v.y); v.z = tf32r(v.z); v.w = tf32r(v.w);
        out4[i] = v;
    }
}

// ---------------- LayerNorm (weight only, eps=1e-5), output tf32-rounded ----------------
__global__ void __launch_bounds__(256) ln_kernel(const float* __restrict__ x,
                                                 const float* __restrict__ w,
                                                 float* __restrict__ out)
{
    const int row = blockIdx.x;
    const int tid = threadIdx.x;
    const float4 xv = reinterpret_cast<const float4*>(x + (size_t)row * EDIM)[tid];
    float s  = xv.x + xv.y + xv.z + xv.w;
    float s2 = xv.x*xv.x + xv.y*xv.y + xv.z*xv.z + xv.w*xv.w;
    #pragma unroll
    for (int off = 16; off; off >>= 1) {
        s  += __shfl_xor_sync(0xffffffffu, s,  off);
        s2 += __shfl_xor_sync(0xffffffffu, s2, off);
    }
    __shared__ float sh[16];
    const int warp = tid >> 5, lane = tid & 31;
    if (lane == 0) { sh[warp] = s; sh[warp + 8] = s2; }
    __syncthreads();
    s = 0.f; s2 = 0.f;
    #pragma unroll
    for (int i = 0; i < 8; i++) { s += sh[i]; s2 += sh[i + 8]; }
    const float mu  = s * (1.0f / EDIM);
    const float var = s2 * (1.0f / EDIM) - mu * mu;
    const float inv = rsqrtf(var + 1e-5f);
    const float4 wv = reinterpret_cast<const float4*>(w)[tid];
    float4 o;
    o.x = tf32r((xv.x - mu) * inv * wv.x);
    o.y = tf32r((xv.y - mu) * inv * wv.y);
    o.z = tf32r((xv.z - mu) * inv * wv.z);
    o.w = tf32r((xv.w - mu) * inv * wv.w);
    reinterpret_cast<float4*>(out + (size_t)row * EDIM)[tid] = o;
}

// ---------------- TF32 tensor-core GEMM ----------------
// C[M,N] = A[M,K] @ B[K,N] (+bias)(+res)(relu)(round)
// Block tile 128x128x32, 8 warps (2x4), warp tile 64x32, mma m16n8k8.
// A in shared: m-major, stride 36 (conflict-free frag reads: banks 4*gid+tid4)
// B in shared: k-major, stride 136 (conflict-free frag reads: banks 8*tid4+gid)
#define BM 128
#define BN 128
#define BK 32
#define AS_LD 36
#define BS_LD 136
#define AS_SZ (BM*AS_LD)              // floats per stage
#define BS_SZ (BK*BS_LD)
#define STAGE_SZ (AS_SZ + BS_SZ)
#define GEMM_SMEM (2*STAGE_SZ*4)      // bytes

template<int BIAS, int RES, int RELU, int ROUND>
__global__ void __launch_bounds__(256) mma_gemm(
    const float* __restrict__ A, const float* __restrict__ B,
    const float* __restrict__ bias, const float* __restrict__ res,
    float* __restrict__ C, int M, int N, int K)
{
    extern __shared__ float sm[];
    const uint32_t smem_u32 = (uint32_t)__cvta_generic_to_shared(sm);

    const int tid  = threadIdx.x;
    const int bx = blockIdx.x, by = blockIdx.y;
    const int warp = tid >> 5, lane = tid & 31;
    const int gid  = lane >> 2, tid4 = lane & 3;
    const int wm = (warp >> 2) * 64;   // warp row offset in block
    const int wn = (warp & 3) * 32;    // warp col offset in block
    const int m0 = by * BM, n0 = bx * BN;

    float c[4][4][4];
    #pragma unroll
    for (int mi = 0; mi < 4; mi++)
        #pragma unroll
        for (int ni = 0; ni < 4; ni++)
            #pragma unroll
            for (int r = 0; r < 4; r++) c[mi][ni][r] = 0.f;

    // ---- async tile loader ----
    auto load_tile = [&](int t, int s) {
        const int k0 = t * BK;
        const uint32_t as_u32 = smem_u32 + (uint32_t)(s * STAGE_SZ) * 4u;
        const uint32_t bs_u32 = as_u32 + (uint32_t)AS_SZ * 4u;
        #pragma unroll
        for (int p = 0; p < 4; p++) {
            const int idx = tid + p * 256;
            const int m = idx >> 3, kq = (idx & 7) << 2;
            CP_ASYNC16(as_u32 + (uint32_t)(m * AS_LD + kq) * 4u,
                       A + (size_t)(m0 + m) * K + k0 + kq);
        }
        #pragma unroll
        for (int p = 0; p < 4; p++) {
            const int idx = tid + p * 256;
            const int k = idx >> 5, nq = (idx & 31) << 2;
            CP_ASYNC16(bs_u32 + (uint32_t)(k * BS_LD + nq) * 4u,
                       B + (size_t)(k0 + k) * N + n0 + nq);
        }
        CP_COMMIT();
    };

    const int T = K / BK;
    load_tile(0, 0);

    for (int t = 0; t < T; t++) {
        const int s = t & 1;
        if (t + 1 < T) { load_tile(t + 1, (t + 1) & 1); CP_WAIT1(); }
        else           { CP_WAIT0(); }
        __syncthreads();

        const float* as = sm + s * STAGE_SZ;
        const float* bs = as + AS_SZ;

        #pragma unroll
        for (int ks = 0; ks < 4; ks++) {
            const int kb = ks * 8;
            uint32_t af[4][4], bf[4][2];
            #pragma unroll
            for (int mi = 0; mi < 4; mi++) {
                const float* p = as + (wm + mi * 16 + gid) * AS_LD + kb + tid4;
                af[mi][0] = __float_as_uint(p[0]);
                af[mi][1] = __float_as_uint(p[8 * AS_LD]);
                af[mi][2] = __float_as_uint(p[4]);
                af[mi][3] = __float_as_uint(p[8 * AS_LD + 4]);
            }
            #pragma unroll
            for (int ni = 0; ni < 4; ni++) {
                const float* p = bs + (kb + tid4) * BS_LD + wn + ni * 8 + gid;
                bf[ni][0] = __float_as_uint(p[0]);
                bf[ni][1] = __float_as_uint(p[4 * BS_LD]);
            }
            #pragma unroll
            for (int mi = 0; mi < 4; mi++)
                #pragma unroll
                for (int ni = 0; ni < 4; ni++) {
                    asm volatile(
                        "mma.sync.aligned.m16n8k8.row.col.f32.tf32.tf32.f32 "
                        "{%0,%1,%2,%3}, {%4,%5,%6,%7}, {%8,%9}, {%0,%1,%2,%3};\n"
                        : "+f"(c[mi][ni][0]), "+f"(c[mi][ni][1]),
                          "+f"(c[mi][ni][2]), "+f"(c[mi][ni][3])
                        : "r"(af[mi][0]), "r"(af[mi][1]), "r"(af[mi][2]), "r"(af[mi][3]),
                          "r"(bf[ni][0]), "r"(bf[ni][1]));
                }
        }
        __syncthreads();
    }

    // ---- epilogue ----
    #pragma unroll
    for (int mi = 0; mi < 4; mi++) {
        #pragma unroll
        for (int ni = 0; ni < 4; ni++) {
            const int row = m0 + wm + mi * 16 + gid;
            const int col = n0 + wn + ni * 8 + tid4 * 2;
            float2 v0 = make_float2(c[mi][ni][0], c[mi][ni][1]);
            float2 v1 = make_float2(c[mi][ni][2], c[mi][ni][3]);
            if (BIAS) {
                const float2 bv = *reinterpret_cast<const float2*>(bias + col);
                v0.x += bv.x; v0.y += bv.y; v1.x += bv.x; v1.y += bv.y;
            }
            if (RES) {
                const float2 r0 = *reinterpret_cast<const float2*>(res + (size_t)row * N + col);
                const float2 r1 = *reinterpret_cast<const float2*>(res + (size_t)(row + 8) * N + col);
                v0.x += r0.x; v0.y += r0.y; v1.x += r1.x; v1.y += r1.y;
            }
            if (RELU) {
                v0.x = fmaxf(v0.x, 0.f); v0.y = fmaxf(v0.y, 0.f);
                v1.x = fmaxf(v1.x, 0.f); v1.y = fmaxf(v1.y, 0.f);
            }
            if (ROUND) {
                v0.x = tf32r(v0.x); v0.y = tf32r(v0.y);
                v1.x = tf32r(v1.x); v1.y = tf32r(v1.y);
            }
            *reinterpret_cast<float2*>(C + (size_t)row * N + col) = v0;
            *reinterpret_cast<float2*>(C + (size_t)(row + 8) * N + col) = v1;
        }
    }
}

// ---------------- Causal flash attention, fp32, 64x64 tiles ----------------
#define SM_LD 65
__global__ void __launch_bounds__(256) attn_kernel(
    const float* __restrict__ Q, const float* __restrict__ K,
    const float* __restrict__ V, float* __restrict__ Y)
{
    extern __shared__ float smem[];
    float* Qs = smem;
    float* Ks = Qs + 64 * SM_LD;
    float* Vs = Ks + 64 * SM_LD;
    float* Ps = Vs + 64 * SM_LD;

    const int qt = blockIdx.x, h = blockIdx.y, b = blockIdx.z;
    const int tid = threadIdx.x;
    const int c0 = (tid & 15) << 2;
    const int r0 = (tid >> 4) << 2;
    const float scale = 0.03125f;     // E^-0.5

    for (int i = tid; i < 64 * 16; i += 256) {
        const int r = i >> 4, d4 = (i & 15) << 2;
        const float4 qv = *reinterpret_cast<const float4*>(
            Q + ((size_t)(b * TSEQ + qt * 64 + r)) * EDIM + h * HS + d4);
        Qs[r * SM_LD + d4 + 0] = qv.x * scale;
        Qs[r * SM_LD + d4 + 1] = qv.y * scale;
        Qs[r * SM_LD + d4 + 2] = qv.z * scale;
        Qs[r * SM_LD + d4 + 3] = qv.w * scale;
    }

    float m_i[4], l_i[4], o[4][4];
    #pragma unroll
    for (int i = 0; i < 4; i++) {
        m_i[i] = -1e30f; l_i[i] = 0.f;
        #pragma unroll
        for (int j = 0; j < 4; j++) o[i][j] = 0.f;
    }
    __syncthreads();

    for (int kt = 0; kt <= qt; kt++) {
        for (int i = tid; i < 64 * 16; i += 256) {
            const int r = i >> 4, d4 = (i & 15) << 2;
            const size_t gbase = ((size_t)(b * TSEQ + kt * 64 + r)) * EDIM + h * HS + d4;
            const float4 kv = *reinterpret_cast<const float4*>(K + gbase);
            const float4 vv = *reinterpret_cast<const float4*>(V + gbase);
            Ks[r * SM_LD + d4 + 0] = kv.x; Ks[r * SM_LD + d4 + 1] = kv.y;
            Ks[r * SM_LD + d4 + 2] = kv.z; Ks[r * SM_LD + d4 + 3] = kv.w;
            Vs[r * SM_LD + d4 + 0] = vv.x; Vs[r * SM_LD + d4 + 1] = vv.y;
            Vs[r * SM_LD + d4 + 2] = vv.z; Vs[r * SM_LD + d4 + 3] = vv.w;
        }
        __syncthreads();

        float s4[4][4];
        #pragma unroll
        for (int i = 0; i < 4; i++)
            #pragma unroll
            for (int j = 0; j < 4; j++) s4[i][j] = 0.f;
        #pragma unroll 8
        for (int d = 0; d < 64; d++) {
            float qr[4], kc[4];
            #pragma unroll
            for (int i = 0; i < 4; i++) qr[i] = Qs[(r0 + i) * SM_LD + d];
            #pragma unroll
            for (int j = 0; j < 4; j++) kc[j] = Ks[(c0 + j) * SM_LD + d];
            #pragma unroll
            for (int i = 0; i < 4; i++)
                #pragma unroll
                for (int j = 0; j < 4; j++)
                    s4[i][j] = fmaf(qr[i], kc[j], s4[i][j]);
        }

        if (kt == qt) {
            #pragma unroll
            for (int i = 0; i < 4; i++)
                #pragma unroll
                for (int j = 0; j < 4; j++)
                    if (c0 + j > r0 + i) s4[i][j] = -1e30f;
        }

        float mx[4];
        #pragma unroll
        for (int i = 0; i < 4; i++) {
            float v = fmaxf(fmaxf(s4[i][0], s4[i][1]), fmaxf(s4[i][2], s4[i][3]));
            #pragma unroll
            for (int off = 8; off; off >>= 1)
                v = fmaxf(v, __shfl_xor_sync(0xffffffffu, v, off, 16));
            mx[i] = v;
        }

        float alpha[4];
        #pragma unroll
        for (int i = 0; i < 4; i++) {
            const float m_new = fmaxf(m_i[i], mx[i]);
            alpha[i] = __expf(m_i[i] - m_new);
            m_i[i] = m_new;
            float r = 0.f;
            #pragma unroll
            for (int j = 0; j < 4; j++) {
                const float p = __expf(s4[i][j] - m_new);
                s4[i][j] = p;
                r += p;
            }
            #pragma unroll
            for (int off = 8; off; off >>= 1)
                r += __shfl_xor_sync(0xffffffffu, r, off, 16);
            l_i[i] = l_i[i] * alpha[i] + r;
        }

        #pragma unroll
        for (int i = 0; i < 4; i++) {
            #pragma unroll
            for (int j = 0; j < 4; j++) {
                Ps[(r0 + i) * SM_LD + c0 + j] = s4[i][j];
                o[i][j] *= alpha[i];
            }
        }
        __syncthreads();

        #pragma unroll 8
        for (int k = 0; k < 64; k++) {
            float pr[4], vc[4];
            #pragma unroll
            for (int i = 0; i < 4; i++) pr[i] = Ps[(r0 + i) * SM_LD + k];
            #pragma unroll
            for (int j = 0; j < 4; j++) vc[j] = Vs[k * SM_LD + c0 + j];
            #pragma unroll
            for (int i = 0; i < 4; i++)
                #pragma unroll
                for (int j = 0; j < 4; j++)
                    o[i][j] = fmaf(pr[i], vc[j], o[i][j]);
        }
        __syncthreads();
    }

    #pragma unroll
    for (int i = 0; i < 4; i++) {
        const float inv = 1.0f / l_i[i];
        float4 ov;
        ov.x = tf32r(o[i][0] * inv); ov.y = tf32r(o[i][1] * inv);
        ov.z = tf32r(o[i][2] * inv); ov.w = tf32r(o[i][3] * inv);
        *reinterpret_cast<float4*>(
            Y + ((size_t)(b * TSEQ + qt * 64 + r0 + i)) * EDIM + h * HS + c0) = ov;
    }
}

// ---------------- launch ----------------
extern "C" void kernel_launch(void* const* d_in, const int* in_sizes, int n_in,
                              void* d_out, int out_size)
{
    const float* x    = (const float*)d_in[0];
    const float* Wq   = (const float*)d_in[1];
    const float* Wk   = (const float*)d_in[2];
    const float* Wv   = (const float*)d_in[3];
    const float* Wo   = (const float*)d_in[4];
    const float* bo   = (const float*)d_in[5];
    const float* ln1w = (const float*)d_in[6];
    const float* ln2w = (const float*)d_in[7];
    const float* W1   = (const float*)d_in[8];
    const float* b1   = (const float*)d_in[9];
    const float* W2   = (const float*)d_in[10];
    const float* b2   = (const float*)d_in[11];
    float* out = (float*)d_out;

    float *h, *q, *k, *v, *y, *x2, *h2, *ff;
    float *wq, *wk, *wv, *wo, *w1, *w2;
    cudaGetSymbolAddress((void**)&h,  g_h);
    cudaGetSymbolAddress((void**)&q,  g_q);
    cudaGetSymbolAddress((void**)&k,  g_k);
    cudaGetSymbolAddress((void**)&v,  g_v);
    cudaGetSymbolAddress((void**)&y,  g_y);
    cudaGetSymbolAddress((void**)&x2, g_x2);
    cudaGetSymbolAddress((void**)&h2, g_h2);
    cudaGetSymbolAddress((void**)&ff, g_ff);
    cudaGetSymbolAddress((void**)&wq, g_wq);
    cudaGetSymbolAddress((void**)&wk, g_wk);
    cudaGetSymbolAddress((void**)&wv, g_wv);
    cudaGetSymbolAddress((void**)&wo, g_wo);
    cudaGetSymbolAddress((void**)&w1, g_w1);
    cudaGetSymbolAddress((void**)&w2, g_w2);

    const int smem_attn = 4 * 64 * SM_LD * (int)sizeof(float);
    cudaFuncSetAttribute(attn_kernel, cudaFuncAttributeMaxDynamicSharedMemorySize, smem_attn);
    cudaFuncSetAttribute(mma_gemm<0,0,0,0>, cudaFuncAttributeMaxDynamicSharedMemorySize, GEMM_SMEM);
    cudaFuncSetAttribute(mma_gemm<1,1,0,0>, cudaFuncAttributeMaxDynamicSharedMemorySize, GEMM_SMEM);
    cudaFuncSetAttribute(mma_gemm<1,0,1,1>, cudaFuncAttributeMaxDynamicSharedMemorySize, GEMM_SMEM);

    // 0) pre-round weights to tf32
    const int EE4 = EDIM * EDIM / 4, EF4 = EDIM * FDIM / 4;
    round_kernel<<<1024, 256>>>(Wq, wq, EE4);
    round_kernel<<<1024, 256>>>(Wk, wk, EE4);
    round_kernel<<<1024, 256>>>(Wv, wv, EE4);
    round_kernel<<<1024, 256>>>(Wo, wo, EE4);
    round_kernel<<<2048, 256>>>(W1, w1, EF4);
    round_kernel<<<2048, 256>>>(W2, w2, EF4);

    // 1) LN1 (tf32-rounded output)
    ln_kernel<<<BT, 256>>>(x, ln1w, h);

    // 2-4) QKV projections (tf32 mma)
    dim3 gE(EDIM / BN, BT / BM);
    mma_gemm<0,0,0,0><<<gE, 256, GEMM_SMEM>>>(h, wq, nullptr, nullptr, q, BT, EDIM, EDIM);
    mma_gemm<0,0,0,0><<<gE, 256, GEMM_SMEM>>>(h, wk, nullptr, nullptr, k, BT, EDIM, EDIM);
    mma_gemm<0,0,0,0><<<gE, 256, GEMM_SMEM>>>(h, wv, nullptr, nullptr, v, BT, EDIM, EDIM);

    // 5) causal attention (fp32, y tf32-rounded)
    attn_kernel<<<dim3(TSEQ / 64, NHEAD, BATCH), 256, smem_attn>>>(q, k, v, y);

    // 6) out projection + bias + residual(x)
    mma_gemm<1,1,0,0><<<gE, 256, GEMM_SMEM>>>(y, wo, bo, x, x2, BT, EDIM, EDIM);

    // 7) LN2 (tf32-rounded output)
    ln_kernel<<<BT, 256>>>(x2, ln2w, h2);

    // 8) FFN up + relu (tf32-rounded output)
    dim3 gF(FDIM / BN, BT / BM);
    mma_gemm<1,0,1,1><<<gF, 256, GEMM_SMEM>>>(h2, w1, b1, nullptr, ff, BT, FDIM, EDIM);

    // 9) FFN down + bias + residual(x2) -> out
    mma_gemm<1,1,0,0><<<gE, 256, GEMM_SMEM>>>(ff, w2, b2, x2, out, BT, EDIM, FDIM);
}

// round 6
// speedup vs baseline: 2.9755x; 1.3484x over previous
#include <cuda_runtime.h>
#include <cuda_fp16.h>
#include <cstdint>
#include <math.h>

// Problem constants
#define BATCH 4
#define TSEQ  2048
#define EDIM  1024
#define FDIM  4096
#define NHEAD 16
#define HS    64
#define BT    (BATCH*TSEQ)   // 8192 rows

// single dynamic smem symbol shared by all kernels
extern __shared__ char dyn_smem[];

// ---------------- scratch (no allocation allowed) ----------------
__device__ __half g_h [BT*(size_t)EDIM];   // LN1 out (half)
__device__ float  g_q [BT*(size_t)EDIM];
__device__ float  g_k [BT*(size_t)EDIM];
__device__ float  g_v [BT*(size_t)EDIM];
__device__ __half g_y [BT*(size_t)EDIM];   // attention out (half)
__device__ float  g_x2[BT*(size_t)EDIM];
__device__ __half g_h2[BT*(size_t)EDIM];   // LN2 out (half)
__device__ __half g_ff[BT*(size_t)FDIM];   // FFN1 out (half)
// transposed + fp16 weights, [N][K] K-major
__device__ __half g_wq[EDIM*(size_t)EDIM];
__device__ __half g_wk[EDIM*(size_t)EDIM];
__device__ __half g_wv[EDIM*(size_t)EDIM];
__device__ __half g_wo[EDIM*(size_t)EDIM];
__device__ __half g_w1[EDIM*(size_t)FDIM];
__device__ __half g_w2[FDIM*(size_t)EDIM];

// ---------------- helpers ----------------
#define CP_ASYNC16(dst, src) \
    asm volatile("cp.async.cg.shared.global [%0], [%1], 16;\n" :: "r"(dst), "l"(src))
#define CP_COMMIT() asm volatile("cp.async.commit_group;\n" ::)
#define CP_WAIT1()  asm volatile("cp.async.wait_group 1;\n" ::)
#define CP_WAIT0()  asm volatile("cp.async.wait_group 0;\n" ::)

__device__ __forceinline__ uint32_t smem_u32_of(const void* p) {
    uint32_t a;
    asm("{ .reg .u64 t; cvta.to.shared.u64 t, %1; cvt.u32.u64 %0, t; }" : "=r"(a) : "l"(p));
    return a;
}

// ---------------- transpose + fp16-convert weights: out[N][K] = half(in[K][N]) ----------------
__global__ void __launch_bounds__(256) transpose_half(const float* __restrict__ in,
                                                      __half* __restrict__ out,
                                                      int K, int N)
{
    __shared__ float t[32][33];
    const int bx = blockIdx.x * 32;  // N offset
    const int by = blockIdx.y * 32;  // K offset
    const int tx = threadIdx.x, ty = threadIdx.y;   // 32 x 8
    #pragma unroll
    for (int i = 0; i < 32; i += 8)
        t[ty + i][tx] = in[(size_t)(by + ty + i) * N + bx + tx];
    __syncthreads();
    #pragma unroll
    for (int i = 0; i < 32; i += 8)
        out[(size_t)(bx + ty + i) * K + by + tx] = __float2half(t[tx][ty + i]);
}

// ---------------- LayerNorm (weight only, eps=1e-5), output fp16 ----------------
__global__ void __launch_bounds__(256) ln_kernel(const float* __restrict__ x,
                                                 const float* __restrict__ w,
                                                 __half* __restrict__ out)
{
    const int row = blockIdx.x;
    const int tid = threadIdx.x;
    const float4 xv = reinterpret_cast<const float4*>(x + (size_t)row * EDIM)[tid];
    float s  = xv.x + xv.y + xv.z + xv.w;
    float s2 = xv.x*xv.x + xv.y*xv.y + xv.z*xv.z + xv.w*xv.w;
    #pragma unroll
    for (int off = 16; off; off >>= 1) {
        s  += __shfl_xor_sync(0xffffffffu, s,  off);
        s2 += __shfl_xor_sync(0xffffffffu, s2, off);
    }
    __shared__ float sh[16];
    const int warp = tid >> 5, lane = tid & 31;
    if (lane == 0) { sh[warp] = s; sh[warp + 8] = s2; }
    __syncthreads();
    s = 0.f; s2 = 0.f;
    #pragma unroll
    for (int i = 0; i < 8; i++) { s += sh[i]; s2 += sh[i + 8]; }
    const float mu  = s * (1.0f / EDIM);
    const float var = s2 * (1.0f / EDIM) - mu * mu;
    const float inv = rsqrtf(var + 1e-5f);
    const float4 wv = reinterpret_cast<const float4*>(w)[tid];
    __half2 o01 = __floats2half2_rn((xv.x - mu) * inv * wv.x, (xv.y - mu) * inv * wv.y);
    __half2 o23 = __floats2half2_rn((xv.z - mu) * inv * wv.z, (xv.w - mu) * inv * wv.w);
    uint2 pk;
    pk.x = *reinterpret_cast<uint32_t*>(&o01);
    pk.y = *reinterpret_cast<uint32_t*>(&o23);
    reinterpret_cast<uint2*>(out + (size_t)row * EDIM)[tid] = pk;
}

// ---------------- fp16 tensor-core GEMM (legacy mma.sync m16n8k16) ----------------
// C[M,N] = A[M,K] @ Bt[N,K]^T  (+bias)(+res)(relu)
// Block tile 128x128x64, 2 stages, 256 threads (8 warps, 2x4), warp tile 64x32.
// A smem [128][72] halfs, B smem [128][72] halfs (padded stride -> conflict-free LDS.32)
#define BM 128
#define BN 128
#define BK 64
#define SLD 72                                  // padded stride in halfs
#define A_ST_BYTES (BM*SLD*2)                   // 18432
#define B_ST_BYTES (BN*SLD*2)                   // 18432
#define STAGE_BYTES (A_ST_BYTES + B_ST_BYTES)   // 36864
#define GEMM_SMEM_BYTES (2*STAGE_BYTES)         // 73728

__device__ __forceinline__ void store_c2(float* C, size_t idx, float v0, float v1) {
    *reinterpret_cast<float2*>(C + idx) = make_float2(v0, v1);
}
__device__ __forceinline__ void store_c2(__half* C, size_t idx, float v0, float v1) {
    __half2 h = __floats2half2_rn(v0, v1);
    *reinterpret_cast<__half2*>(C + idx) = h;
}

template<int BIAS, int RES, int RELU, typename OutT>
__global__ void __launch_bounds__(256) hgemm(
    const __half* __restrict__ A, const __half* __restrict__ Bt,
    const float* __restrict__ bias, const float* __restrict__ res,
    OutT* __restrict__ C, int M, int N, int K)
{
    const uint32_t smem_u = smem_u32_of(dyn_smem);
    const int tid = threadIdx.x;
    const int warp = tid >> 5, lane = tid & 31;
    const int gid = lane >> 2, t4 = lane & 3;
    const int wm = (warp >> 2) * 64;   // warp row offset
    const int wn = (warp & 3) * 32;    // warp col offset
    const int m0 = blockIdx.y * BM, n0 = blockIdx.x * BN;

    float c[4][4][4];
    #pragma unroll
    for (int mi = 0; mi < 4; mi++)
        #pragma unroll
        for (int ni = 0; ni < 4; ni++)
            #pragma unroll
            for (int r = 0; r < 4; r++) c[mi][ni][r] = 0.f;

    // loader: per stage, A: 1024 16B-chunks, B: 1024 chunks; 256 threads x 4 each
    auto load_stage = [&](int t, int buf) {
        const int k0 = t * BK;
        const uint32_t as = smem_u + buf * STAGE_BYTES;
        const uint32_t bs = as + A_ST_BYTES;
        #pragma unroll
        for (int i = 0; i < 4; i++) {
            const int ch = tid + i * 256;
            const int row = ch >> 3, kc = ch & 7;
            CP_ASYNC16(as + (uint32_t)(row * (SLD * 2) + kc * 16),
                       A + (size_t)(m0 + row) * K + k0 + kc * 8);
        }
        #pragma unroll
        for (int i = 0; i < 4; i++) {
            const int ch = tid + i * 256;
            const int row = ch >> 3, kc = ch & 7;
            CP_ASYNC16(bs + (uint32_t)(row * (SLD * 2) + kc * 16),
                       Bt + (size_t)(n0 + row) * K + k0 + kc * 8);
        }
        CP_COMMIT();
    };

    const int T = K / BK;
    load_stage(0, 0);

    for (int t = 0; t < T; t++) {
        const int buf = t & 1;
        if (t + 1 < T) { load_stage(t + 1, (t + 1) & 1); CP_WAIT1(); }
        else           { CP_WAIT0(); }
        __syncthreads();

        const __half* as = reinterpret_cast<const __half*>(dyn_smem + buf * STAGE_BYTES);
        const __half* bs = reinterpret_cast<const __half*>(dyn_smem + buf * STAGE_BYTES + A_ST_BYTES);

        #pragma unroll
        for (int ks = 0; ks < 4; ks++) {
            const int kb = ks * 16;
            uint32_t af[4][4], bf[4][2];
            #pragma unroll
            for (int mi = 0; mi < 4; mi++) {
                const __half* p = as + (wm + mi * 16 + gid) * SLD + kb + 2 * t4;
                af[mi][0] = *reinterpret_cast<const uint32_t*>(p);
                af[mi][1] = *reinterpret_cast<const uint32_t*>(p + 8 * SLD);
                af[mi][2] = *reinterpret_cast<const uint32_t*>(p + 8);
                af[mi][3] = *reinterpret_cast<const uint32_t*>(p + 8 * SLD + 8);
            }
            #pragma unroll
            for (int ni = 0; ni < 4; ni++) {
                const __half* p = bs + (wn + ni * 8 + gid) * SLD + kb + 2 * t4;
                bf[ni][0] = *reinterpret_cast<const uint32_t*>(p);
                bf[ni][1] = *reinterpret_cast<const uint32_t*>(p + 8);
            }
            #pragma unroll
            for (int mi = 0; mi < 4; mi++)
                #pragma unroll
                for (int ni = 0; ni < 4; ni++) {
                    asm volatile(
                        "mma.sync.aligned.m16n8k16.row.col.f32.f16.f16.f32 "
                        "{%0,%1,%2,%3}, {%4,%5,%6,%7}, {%8,%9}, {%0,%1,%2,%3};\n"
                        : "+f"(c[mi][ni][0]), "+f"(c[mi][ni][1]),
                          "+f"(c[mi][ni][2]), "+f"(c[mi][ni][3])
                        : "r"(af[mi][0]), "r"(af[mi][1]), "r"(af[mi][2]), "r"(af[mi][3]),
                          "r"(bf[ni][0]), "r"(bf[ni][1]));
                }
        }
        __syncthreads();
    }

    // ---- epilogue: direct stores ----
    #pragma unroll
    for (int mi = 0; mi < 4; mi++) {
        #pragma unroll
        for (int ni = 0; ni < 4; ni++) {
            const int row = m0 + wm + mi * 16 + gid;
            const int col = n0 + wn + ni * 8 + t4 * 2;
            float v0 = c[mi][ni][0], v1 = c[mi][ni][1];
            float v2 = c[mi][ni][2], v3 = c[mi][ni][3];
            if (BIAS) {
                const float2 bv = *reinterpret_cast<const float2*>(bias + col);
                v0 += bv.x; v1 += bv.y; v2 += bv.x; v3 += bv.y;
            }
            if (RES) {
                const float2 r0 = *reinterpret_cast<const float2*>(res + (size_t)row * N + col);
                const float2 r1 = *reinterpret_cast<const float2*>(res + (size_t)(row + 8) * N + col);
                v0 += r0.x; v1 += r0.y; v2 += r1.x; v3 += r1.y;
            }
            if (RELU) {
                v0 = fmaxf(v0, 0.f); v1 = fmaxf(v1, 0.f);
                v2 = fmaxf(v2, 0.f); v3 = fmaxf(v3, 0.f);
            }
            store_c2(C, (size_t)row * N + col, v0, v1);
            store_c2(C, (size_t)(row + 8) * N + col, v2, v3);
        }
    }
}

// ---------------- Causal flash attention, fp32, 64x64 tiles ----------------
#define SM_LD 65
__global__ void __launch_bounds__(256) attn_kernel(
    const float* __restrict__ Q, const float* __restrict__ K,
    const float* __restrict__ V, __half* __restrict__ Y)
{
    float* smem = reinterpret_cast<float*>(dyn_smem);
    float* Qs = smem;
    float* Ks = Qs + 64 * SM_LD;
    float* Vs = Ks + 64 * SM_LD;
    float* Ps = Vs + 64 * SM_LD;

    const int qt = blockIdx.x, h = blockIdx.y, b = blockIdx.z;
    const int tid = threadIdx.x;
    const int c0 = (tid & 15) << 2;
    const int r0 = (tid >> 4) << 2;
    const float scale = 0.03125f;     // E^-0.5

    for (int i = tid; i < 64 * 16; i += 256) {
        const int r = i >> 4, d4 = (i & 15) << 2;
        const float4 qv = *reinterpret_cast<const float4*>(
            Q + ((size_t)(b * TSEQ + qt * 64 + r)) * EDIM + h * HS + d4);
        Qs[r * SM_LD + d4 + 0] = qv.x * scale;
        Qs[r * SM_LD + d4 + 1] = qv.y * scale;
        Qs[r * SM_LD + d4 + 2] = qv.z * scale;
        Qs[r * SM_LD + d4 + 3] = qv.w * scale;
    }

    float m_i[4], l_i[4], o[4][4];
    #pragma unroll
    for (int i = 0; i < 4; i++) {
        m_i[i] = -1e30f; l_i[i] = 0.f;
        #pragma unroll
        for (int j = 0; j < 4; j++) o[i][j] = 0.f;
    }
    __syncthreads();

    for (int kt = 0; kt <= qt; kt++) {
        for (int i = tid; i < 64 * 16; i += 256) {
            const int r = i >> 4, d4 = (i & 15) << 2;
            const size_t gbase = ((size_t)(b * TSEQ + kt * 64 + r)) * EDIM + h * HS + d4;
            const float4 kv = *reinterpret_cast<const float4*>(K + gbase);
            const float4 vv = *reinterpret_cast<const float4*>(V + gbase);
            Ks[r * SM_LD + d4 + 0] = kv.x; Ks[r * SM_LD + d4 + 1] = kv.y;
            Ks[r * SM_LD + d4 + 2] = kv.z; Ks[r * SM_LD + d4 + 3] = kv.w;
            Vs[r * SM_LD + d4 + 0] = vv.x; Vs[r * SM_LD + d4 + 1] = vv.y;
            Vs[r * SM_LD + d4 + 2] = vv.z; Vs[r * SM_LD + d4 + 3] = vv.w;
        }
        __syncthreads();

        float s4[4][4];
        #pragma unroll
        for (int i = 0; i < 4; i++)
            #pragma unroll
            for (int j = 0; j < 4; j++) s4[i][j] = 0.f;
        #pragma unroll 8
        for (int d = 0; d < 64; d++) {
            float qr[4], kc[4];
            #pragma unroll
            for (int i = 0; i < 4; i++) qr[i] = Qs[(r0 + i) * SM_LD + d];
            #pragma unroll
            for (int j = 0; j < 4; j++) kc[j] = Ks[(c0 + j) * SM_LD + d];
            #pragma unroll
            for (int i = 0; i < 4; i++)
                #pragma unroll
                for (int j = 0; j < 4; j++)
                    s4[i][j] = fmaf(qr[i], kc[j], s4[i][j]);
        }

        if (kt == qt) {
            #pragma unroll
            for (int i = 0; i < 4; i++)
                #pragma unroll
                for (int j = 0; j < 4; j++)
                    if (c0 + j > r0 + i) s4[i][j] = -1e30f;
        }

        float mx[4];
        #pragma unroll
        for (int i = 0; i < 4; i++) {
            float v = fmaxf(fmaxf(s4[i][0], s4[i][1]), fmaxf(s4[i][2], s4[i][3]));
            #pragma unroll
            for (int off = 8; off; off >>= 1)
                v = fmaxf(v, __shfl_xor_sync(0xffffffffu, v, off, 16));
            mx[i] = v;
        }

        float alpha[4];
        #pragma unroll
        for (int i = 0; i < 4; i++) {
            const float m_new = fmaxf(m_i[i], mx[i]);
            alpha[i] = __expf(m_i[i] - m_new);
            m_i[i] = m_new;
            float r = 0.f;
            #pragma unroll
            for (int j = 0; j < 4; j++) {
                const float p = __expf(s4[i][j] - m_new);
                s4[i][j] = p;
                r += p;
            }
            #pragma unroll
            for (int off = 8; off; off >>= 1)
                r += __shfl_xor_sync(0xffffffffu, r, off, 16);
            l_i[i] = l_i[i] * alpha[i] + r;
        }

        #pragma unroll
        for (int i = 0; i < 4; i++) {
            #pragma unroll
            for (int j = 0; j < 4; j++) {
                Ps[(r0 + i) * SM_LD + c0 + j] = s4[i][j];
                o[i][j] *= alpha[i];
            }
        }
        __syncthreads();

        #pragma unroll 8
        for (int k = 0; k < 64; k++) {
            float pr[4], vc[4];
            #pragma unroll
            for (int i = 0; i < 4; i++) pr[i] = Ps[(r0 + i) * SM_LD + k];
            #pragma unroll
            for (int j = 0; j < 4; j++) vc[j] = Vs[k * SM_LD + c0 + j];
            #pragma unroll
            for (int i = 0; i < 4; i++)
                #pragma unroll
                for (int j = 0; j < 4; j++)
                    o[i][j] = fmaf(pr[i], vc[j], o[i][j]);
        }
        __syncthreads();
    }

    #pragma unroll
    for (int i = 0; i < 4; i++) {
        const float inv = 1.0f / l_i[i];
        __half2 h01 = __floats2half2_rn(o[i][0] * inv, o[i][1] * inv);
        __half2 h23 = __floats2half2_rn(o[i][2] * inv, o[i][3] * inv);
        __half* yp = Y + ((size_t)(b * TSEQ + qt * 64 + r0 + i)) * EDIM + h * HS + c0;
        *reinterpret_cast<__half2*>(yp)     = h01;
        *reinterpret_cast<__half2*>(yp + 2) = h23;
    }
}

// ---------------- launch ----------------
extern "C" void kernel_launch(void* const* d_in, const int* in_sizes, int n_in,
                              void* d_out, int out_size)
{
    const float* x    = (const float*)d_in[0];
    const float* Wq   = (const float*)d_in[1];
    const float* Wk   = (const float*)d_in[2];
    const float* Wv   = (const float*)d_in[3];
    const float* Wo   = (const float*)d_in[4];
    const float* bo   = (const float*)d_in[5];
    const float* ln1w = (const float*)d_in[6];
    const float* ln2w = (const float*)d_in[7];
    const float* W1   = (const float*)d_in[8];
    const float* b1   = (const float*)d_in[9];
    const float* W2   = (const float*)d_in[10];
    const float* b2   = (const float*)d_in[11];
    float* out = (float*)d_out;

    __half *h, *y, *h2, *ff, *wq, *wk, *wv, *wo, *w1, *w2;
    float *q, *k, *v, *x2;
    cudaGetSymbolAddress((void**)&h,  g_h);
    cudaGetSymbolAddress((void**)&q,  g_q);
    cudaGetSymbolAddress((void**)&k,  g_k);
    cudaGetSymbolAddress((void**)&v,  g_v);
    cudaGetSymbolAddress((void**)&y,  g_y);
    cudaGetSymbolAddress((void**)&x2, g_x2);
    cudaGetSymbolAddress((void**)&h2, g_h2);
    cudaGetSymbolAddress((void**)&ff, g_ff);
    cudaGetSymbolAddress((void**)&wq, g_wq);
    cudaGetSymbolAddress((void**)&wk, g_wk);
    cudaGetSymbolAddress((void**)&wv, g_wv);
    cudaGetSymbolAddress((void**)&wo, g_wo);
    cudaGetSymbolAddress((void**)&w1, g_w1);
    cudaGetSymbolAddress((void**)&w2, g_w2);

    const int smem_attn = 4 * 64 * SM_LD * (int)sizeof(float);
    cudaFuncSetAttribute(attn_kernel, cudaFuncAttributeMaxDynamicSharedMemorySize, smem_attn);
    cudaFuncSetAttribute(hgemm<0,0,0,float>,  cudaFuncAttributeMaxDynamicSharedMemorySize, GEMM_SMEM_BYTES);
    cudaFuncSetAttribute(hgemm<1,1,0,float>,  cudaFuncAttributeMaxDynamicSharedMemorySize, GEMM_SMEM_BYTES);
    cudaFuncSetAttribute(hgemm<1,0,1,__half>, cudaFuncAttributeMaxDynamicSharedMemorySize, GEMM_SMEM_BYTES);

    // 0) transpose + fp16-convert weights into [N][K]
    dim3 tb(32, 8);
    transpose_half<<<dim3(EDIM/32, EDIM/32), tb>>>(Wq, wq, EDIM, EDIM);
    transpose_half<<<dim3(EDIM/32, EDIM/32), tb>>>(Wk, wk, EDIM, EDIM);
    transpose_half<<<dim3(EDIM/32, EDIM/32), tb>>>(Wv, wv, EDIM, EDIM);
    transpose_half<<<dim3(EDIM/32, EDIM/32), tb>>>(Wo, wo, EDIM, EDIM);
    transpose_half<<<dim3(FDIM/32, EDIM/32), tb>>>(W1, w1, EDIM, FDIM);
    transpose_half<<<dim3(EDIM/32, FDIM/32), tb>>>(W2, w2, FDIM, EDIM);

    // 1) LN1 (fp16 out)
    ln_kernel<<<BT, 256>>>(x, ln1w, h);

    // 2-4) QKV projections (fp16 mma, fp32 out)
    dim3 gE(EDIM / BN, BT / BM);
    hgemm<0,0,0,float><<<gE, 256, GEMM_SMEM_BYTES>>>(h, wq, nullptr, nullptr, q, BT, EDIM, EDIM);
    hgemm<0,0,0,float><<<gE, 256, GEMM_SMEM_BYTES>>>(h, wk, nullptr, nullptr, k, BT, EDIM, EDIM);
    hgemm<0,0,0,float><<<gE, 256, GEMM_SMEM_BYTES>>>(h, wv, nullptr, nullptr, v, BT, EDIM, EDIM);

    // 5) causal attention (fp32 math, fp16 y out)
    attn_kernel<<<dim3(TSEQ / 64, NHEAD, BATCH), 256, smem_attn>>>(q, k, v, y);

    // 6) out projection + bias + residual(x) -> x2 (fp32)
    hgemm<1,1,0,float><<<gE, 256, GEMM_SMEM_BYTES>>>(y, wo, bo, x, x2, BT, EDIM, EDIM);

    // 7) LN2 (fp16 out)
    ln_kernel<<<BT, 256>>>(x2, ln2w, h2);

    // 8) FFN up + relu (fp16 out)
    dim3 gF(FDIM / BN, BT / BM);
    hgemm<1,0,1,__half><<<gF, 256, GEMM_SMEM_BYTES>>>(h2, w1, b1, nullptr, ff, BT, FDIM, EDIM);

    // 9) FFN down + bias + residual(x2) -> out (fp32)
    hgemm<1,1,0,float><<<gE, 256, GEMM_SMEM_BYTES>>>(ff, w2, b2, x2, out, BT, EDIM, FDIM);
}

// round 7
// speedup vs baseline: 5.8305x; 1.9595x over previous
#include <cuda_runtime.h>
#include <cuda_fp16.h>
#include <cstdint>
#include <math.h>

// Problem constants
#define BATCH 4
#define TSEQ  2048
#define EDIM  1024
#define FDIM  4096
#define NHEAD 16
#define HS    64
#define BT    (BATCH*TSEQ)   // 8192 rows

// single dynamic smem symbol shared by all kernels
extern __shared__ char dyn_smem[];

// ---------------- scratch (no allocation allowed) ----------------
__device__ __half g_h [BT*(size_t)EDIM];   // LN1 out
__device__ __half g_q [BT*(size_t)EDIM];   // Q (fp16, pre-scaled via Wq)
__device__ __half g_k [BT*(size_t)EDIM];
__device__ __half g_v [BT*(size_t)EDIM];
__device__ __half g_y [BT*(size_t)EDIM];   // attention out
__device__ float  g_x2[BT*(size_t)EDIM];
__device__ __half g_h2[BT*(size_t)EDIM];   // LN2 out
__device__ __half g_ff[BT*(size_t)FDIM];   // FFN1 out
// transposed + fp16 weights, [N][K] K-major
__device__ __half g_wq[EDIM*(size_t)EDIM];
__device__ __half g_wk[EDIM*(size_t)EDIM];
__device__ __half g_wv[EDIM*(size_t)EDIM];
__device__ __half g_wo[EDIM*(size_t)EDIM];
__device__ __half g_w1[EDIM*(size_t)FDIM];
__device__ __half g_w2[FDIM*(size_t)EDIM];

// ---------------- helpers ----------------
#define CP_ASYNC16(dst, src) \
    asm volatile("cp.async.cg.shared.global [%0], [%1], 16;\n" :: "r"(dst), "l"(src))
#define CP_COMMIT() asm volatile("cp.async.commit_group;\n" ::)
#define CP_WAIT1()  asm volatile("cp.async.wait_group 1;\n" ::)
#define CP_WAIT0()  asm volatile("cp.async.wait_group 0;\n" ::)

__device__ __forceinline__ uint32_t smem_u32_of(const void* p) {
    uint32_t a;
    asm("{ .reg .u64 t; cvta.to.shared.u64 t, %1; cvt.u32.u64 %0, t; }" : "=r"(a) : "l"(p));
    return a;
}
__device__ __forceinline__ uint32_t packh2(float x, float y) {
    __half2 h = __floats2half2_rn(x, y);
    return *reinterpret_cast<uint32_t*>(&h);
}
#define MMA_F16(c0,c1,c2,c3,a0,a1,a2,a3,b0,b1) \
    asm volatile("mma.sync.aligned.m16n8k16.row.col.f32.f16.f16.f32 " \
        "{%0,%1,%2,%3}, {%4,%5,%6,%7}, {%8,%9}, {%0,%1,%2,%3};\n" \
        : "+f"(c0), "+f"(c1), "+f"(c2), "+f"(c3) \
        : "r"(a0), "r"(a1), "r"(a2), "r"(a3), "r"(b0), "r"(b1))

// ---------------- transpose + fp16 + optional scale: out[N][K] = half(in[K][N]*scale) ----------------
__global__ void __launch_bounds__(256) transpose_half(const float* __restrict__ in,
                                                      __half* __restrict__ out,
                                                      int K, int N, float scale)
{
    __shared__ float t[32][33];
    const int bx = blockIdx.x * 32;  // N offset
    const int by = blockIdx.y * 32;  // K offset
    const int tx = threadIdx.x, ty = threadIdx.y;   // 32 x 8
    #pragma unroll
    for (int i = 0; i < 32; i += 8)
        t[ty + i][tx] = in[(size_t)(by + ty + i) * N + bx + tx];
    __syncthreads();
    #pragma unroll
    for (int i = 0; i < 32; i += 8)
        out[(size_t)(bx + ty + i) * K + by + tx] = __float2half(t[tx][ty + i] * scale);
}

// ---------------- LayerNorm (weight only, eps=1e-5), output fp16 ----------------
__global__ void __launch_bounds__(256) ln_kernel(const float* __restrict__ x,
                                                 const float* __restrict__ w,
                                                 __half* __restrict__ out)
{
    const int row = blockIdx.x;
    const int tid = threadIdx.x;
    const float4 xv = reinterpret_cast<const float4*>(x + (size_t)row * EDIM)[tid];
    float s  = xv.x + xv.y + xv.z + xv.w;
    float s2 = xv.x*xv.x + xv.y*xv.y + xv.z*xv.z + xv.w*xv.w;
    #pragma unroll
    for (int off = 16; off; off >>= 1) {
        s  += __shfl_xor_sync(0xffffffffu, s,  off);
        s2 += __shfl_xor_sync(0xffffffffu, s2, off);
    }
    __shared__ float sh[16];
    const int warp = tid >> 5, lane = tid & 31;
    if (lane == 0) { sh[warp] = s; sh[warp + 8] = s2; }
    __syncthreads();
    s = 0.f; s2 = 0.f;
    #pragma unroll
    for (int i = 0; i < 8; i++) { s += sh[i]; s2 += sh[i + 8]; }
    const float mu  = s * (1.0f / EDIM);
    const float var = s2 * (1.0f / EDIM) - mu * mu;
    const float inv = rsqrtf(var + 1e-5f);
    const float4 wv = reinterpret_cast<const float4*>(w)[tid];
    __half2 o01 = __floats2half2_rn((xv.x - mu) * inv * wv.x, (xv.y - mu) * inv * wv.y);
    __half2 o23 = __floats2half2_rn((xv.z - mu) * inv * wv.z, (xv.w - mu) * inv * wv.w);
    uint2 pk;
    pk.x = *reinterpret_cast<uint32_t*>(&o01);
    pk.y = *reinterpret_cast<uint32_t*>(&o23);
    reinterpret_cast<uint2*>(out + (size_t)row * EDIM)[tid] = pk;
}

// ---------------- fp16 tensor-core GEMM (legacy mma.sync m16n8k16) ----------------
#define BM 128
#define BN 128
#define BK 64
#define SLD 72
#define A_ST_BYTES (BM*SLD*2)
#define B_ST_BYTES (BN*SLD*2)
#define STAGE_BYTES (A_ST_BYTES + B_ST_BYTES)
#define GEMM_SMEM_BYTES (2*STAGE_BYTES)

__device__ __forceinline__ void store_c2(float* C, size_t idx, float v0, float v1) {
    *reinterpret_cast<float2*>(C + idx) = make_float2(v0, v1);
}
__device__ __forceinline__ void store_c2(__half* C, size_t idx, float v0, float v1) {
    __half2 h = __floats2half2_rn(v0, v1);
    *reinterpret_cast<__half2*>(C + idx) = h;
}

template<int BIAS, int RES, int RELU, typename OutT>
__global__ void __launch_bounds__(256) hgemm(
    const __half* __restrict__ A, const __half* __restrict__ Bt,
    const float* __restrict__ bias, const float* __restrict__ res,
    OutT* __restrict__ C, int M, int N, int K)
{
    const uint32_t smem_u = smem_u32_of(dyn_smem);
    const int tid = threadIdx.x;
    const int warp = tid >> 5, lane = tid & 31;
    const int gid = lane >> 2, t4 = lane & 3;
    const int wm = (warp >> 2) * 64;
    const int wn = (warp & 3) * 32;
    const int m0 = blockIdx.y * BM, n0 = blockIdx.x * BN;

    float c[4][4][4];
    #pragma unroll
    for (int mi = 0; mi < 4; mi++)
        #pragma unroll
        for (int ni = 0; ni < 4; ni++)
            #pragma unroll
            for (int r = 0; r < 4; r++) c[mi][ni][r] = 0.f;

    auto load_stage = [&](int t, int buf) {
        const int k0 = t * BK;
        const uint32_t as = smem_u + buf * STAGE_BYTES;
        const uint32_t bs = as + A_ST_BYTES;
        #pragma unroll
        for (int i = 0; i < 4; i++) {
            const int ch = tid + i * 256;
            const int row = ch >> 3, kc = ch & 7;
            CP_ASYNC16(as + (uint32_t)(row * (SLD * 2) + kc * 16),
                       A + (size_t)(m0 + row) * K + k0 + kc * 8);
        }
        #pragma unroll
        for (int i = 0; i < 4; i++) {
            const int ch = tid + i * 256;
            const int row = ch >> 3, kc = ch & 7;
            CP_ASYNC16(bs + (uint32_t)(row * (SLD * 2) + kc * 16),
                       Bt + (size_t)(n0 + row) * K + k0 + kc * 8);
        }
        CP_COMMIT();
    };

    const int T = K / BK;
    load_stage(0, 0);

    for (int t = 0; t < T; t++) {
        const int buf = t & 1;
        if (t + 1 < T) { load_stage(t + 1, (t + 1) & 1); CP_WAIT1(); }
        else           { CP_WAIT0(); }
        __syncthreads();

        const __half* as = reinterpret_cast<const __half*>(dyn_smem + buf * STAGE_BYTES);
        const __half* bs = reinterpret_cast<const __half*>(dyn_smem + buf * STAGE_BYTES + A_ST_BYTES);

        #pragma unroll
        for (int ks = 0; ks < 4; ks++) {
            const int kb = ks * 16;
            uint32_t af[4][4], bf[4][2];
            #pragma unroll
            for (int mi = 0; mi < 4; mi++) {
                const __half* p = as + (wm + mi * 16 + gid) * SLD + kb + 2 * t4;
                af[mi][0] = *reinterpret_cast<const uint32_t*>(p);
                af[mi][1] = *reinterpret_cast<const uint32_t*>(p + 8 * SLD);
                af[mi][2] = *reinterpret_cast<const uint32_t*>(p + 8);
                af[mi][3] = *reinterpret_cast<const uint32_t*>(p + 8 * SLD + 8);
            }
            #pragma unroll
            for (int ni = 0; ni < 4; ni++) {
                const __half* p = bs + (wn + ni * 8 + gid) * SLD + kb + 2 * t4;
                bf[ni][0] = *reinterpret_cast<const uint32_t*>(p);
                bf[ni][1] = *reinterpret_cast<const uint32_t*>(p + 8);
            }
            #pragma unroll
            for (int mi = 0; mi < 4; mi++)
                #pragma unroll
                for (int ni = 0; ni < 4; ni++)
                    MMA_F16(c[mi][ni][0], c[mi][ni][1], c[mi][ni][2], c[mi][ni][3],
                            af[mi][0], af[mi][1], af[mi][2], af[mi][3],
                            bf[ni][0], bf[ni][1]);
        }
        __syncthreads();
    }

    #pragma unroll
    for (int mi = 0; mi < 4; mi++) {
        #pragma unroll
        for (int ni = 0; ni < 4; ni++) {
            const int row = m0 + wm + mi * 16 + gid;
            const int col = n0 + wn + ni * 8 + t4 * 2;
            float v0 = c[mi][ni][0], v1 = c[mi][ni][1];
            float v2 = c[mi][ni][2], v3 = c[mi][ni][3];
            if (BIAS) {
                const float2 bv = *reinterpret_cast<const float2*>(bias + col);
                v0 += bv.x; v1 += bv.y; v2 += bv.x; v3 += bv.y;
            }
            if (RES) {
                const float2 r0 = *reinterpret_cast<const float2*>(res + (size_t)row * N + col);
                const float2 r1 = *reinterpret_cast<const float2*>(res + (size_t)(row + 8) * N + col);
                v0 += r0.x; v1 += r0.y; v2 += r1.x; v3 += r1.y;
            }
            if (RELU) {
                v0 = fmaxf(v0, 0.f); v1 = fmaxf(v1, 0.f);
                v2 = fmaxf(v2, 0.f); v3 = fmaxf(v3, 0.f);
            }
            store_c2(C, (size_t)row * N + col, v0, v1);
            store_c2(C, (size_t)(row + 8) * N + col, v2, v3);
        }
    }
}

// ---------------- Flash attention v2, fp16 mma, 128x64 tiles ----------------
// grid (T/128, H, B), 256 threads (8 warps x 16 q-rows). Q pre-scaled (via Wq).
#define AQ   128
#define AKV  64
#define ASLD 72
#define QS_OFF   0
#define KV_OFF   (AQ*ASLD)          // 9216 halfs
#define KV_STAGE (AKV*ASLD)         // 4608 halfs
#define ATTN_SMEM_BYTES ((KV_OFF + 4*KV_STAGE)*2)   // 55296

__global__ void __launch_bounds__(256) attn_kernel(
    const __half* __restrict__ Q, const __half* __restrict__ Kg,
    const __half* __restrict__ Vg, __half* __restrict__ Y)
{
    __half* sm = reinterpret_cast<__half*>(dyn_smem);
    const uint32_t smu = smem_u32_of(sm);
    const int tid = threadIdx.x, warp = tid >> 5, lane = tid & 31;
    const int gid = lane >> 2, t4 = lane & 3;
    const int qi = blockIdx.x, h = blockIdx.y, b = blockIdx.z;
    const int q0 = qi * AQ;
    const int wr = warp * 16;
    const size_t rowbase = (size_t)(b * TSEQ) * EDIM + h * HS;

    // Q tile: 1024 16B chunks
    #pragma unroll
    for (int i = 0; i < 4; i++) {
        const int ch = tid + i * 256;
        const int r = ch >> 3, c8 = ch & 7;
        CP_ASYNC16(smu + (uint32_t)(QS_OFF + r * ASLD + c8 * 8) * 2,
                   Q + rowbase + (size_t)(q0 + r) * EDIM + c8 * 8);
    }
    auto load_kv = [&](int kt, int s) {
        const uint32_t kb = smu + (uint32_t)(KV_OFF + s * 2 * KV_STAGE) * 2;
        const uint32_t vb = kb + KV_STAGE * 2;
        const size_t gk = rowbase + (size_t)(kt * AKV) * EDIM;
        #pragma unroll
        for (int i = 0; i < 2; i++) {
            const int ch = tid + i * 256;
            const int r = ch >> 3, c8 = ch & 7;
            CP_ASYNC16(kb + (uint32_t)(r * ASLD + c8 * 8) * 2, Kg + gk + (size_t)r * EDIM + c8 * 8);
        }
        #pragma unroll
        for (int i = 0; i < 2; i++) {
            const int ch = tid + i * 256;
            const int r = ch >> 3, c8 = ch & 7;
            CP_ASYNC16(vb + (uint32_t)(r * ASLD + c8 * 8) * 2, Vg + gk + (size_t)r * EDIM + c8 * 8);
        }
    };
    load_kv(0, 0);
    CP_COMMIT();

    const int nt = 2 * qi + 2;
    float m_s[2] = {-1e30f, -1e30f}, l_s[2] = {0.f, 0.f};
    float o[8][4];
    #pragma unroll
    for (int i = 0; i < 8; i++)
        #pragma unroll
        for (int j = 0; j < 4; j++) o[i][j] = 0.f;

    for (int kt = 0; kt < nt; kt++) {
        const int buf = kt & 1;
        if (kt + 1 < nt) { load_kv(kt + 1, (kt + 1) & 1); CP_COMMIT(); CP_WAIT1(); }
        else             { CP_WAIT0(); }
        __syncthreads();

        const __half* Qs = sm + QS_OFF;
        const __half* Ks = sm + KV_OFF + buf * 2 * KV_STAGE;
        const __half* Vs = Ks + KV_STAGE;

        // S = Q @ K^T
        float c[8][4];
        #pragma unroll
        for (int i = 0; i < 8; i++)
            #pragma unroll
            for (int j = 0; j < 4; j++) c[i][j] = 0.f;
        #pragma unroll
        for (int ks = 0; ks < 4; ks++) {
            const __half* qp = Qs + (wr + gid) * ASLD + ks * 16 + 2 * t4;
            const uint32_t a0 = *reinterpret_cast<const uint32_t*>(qp);
            const uint32_t a1 = *reinterpret_cast<const uint32_t*>(qp + 8 * ASLD);
            const uint32_t a2 = *reinterpret_cast<const uint32_t*>(qp + 8);
            const uint32_t a3 = *reinterpret_cast<const uint32_t*>(qp + 8 * ASLD + 8);
            #pragma unroll
            for (int ni = 0; ni < 8; ni++) {
                const __half* kp = Ks + (ni * 8 + gid) * ASLD + ks * 16 + 2 * t4;
                const uint32_t b0 = *reinterpret_cast<const uint32_t*>(kp);
                const uint32_t b1 = *reinterpret_cast<const uint32_t*>(kp + 8);
                MMA_F16(c[ni][0], c[ni][1], c[ni][2], c[ni][3], a0, a1, a2, a3, b0, b1);
            }
        }

        // causal mask on diagonal tiles
        if (kt >= 2 * qi) {
            #pragma unroll
            for (int ni = 0; ni < 8; ni++) {
                const int cg = kt * AKV + ni * 8 + 2 * t4;
                const int r0g = q0 + wr + gid, r1g = r0g + 8;
                if (cg     > r0g) c[ni][0] = -1e30f;
                if (cg + 1 > r0g) c[ni][1] = -1e30f;
                if (cg     > r1g) c[ni][2] = -1e30f;
                if (cg + 1 > r1g) c[ni][3] = -1e30f;
            }
        }

        // online softmax (rows gid / gid+8)
        #pragma unroll
        for (int r = 0; r < 2; r++) {
            float mx = -1e30f;
            #pragma unroll
            for (int ni = 0; ni < 8; ni++)
                mx = fmaxf(mx, fmaxf(c[ni][2 * r], c[ni][2 * r + 1]));
            mx = fmaxf(mx, __shfl_xor_sync(0xffffffffu, mx, 1));
            mx = fmaxf(mx, __shfl_xor_sync(0xffffffffu, mx, 2));
            const float m_new = fmaxf(m_s[r], mx);
            const float alpha = __expf(m_s[r] - m_new);
            m_s[r] = m_new;
            float rs = 0.f;
            #pragma unroll
            for (int ni = 0; ni < 8; ni++) {
                const float p0 = __expf(c[ni][2 * r]     - m_new);
                const float p1 = __expf(c[ni][2 * r + 1] - m_new);
                c[ni][2 * r] = p0; c[ni][2 * r + 1] = p1;
                rs += p0 + p1;
            }
            rs += __shfl_xor_sync(0xffffffffu, rs, 1);
            rs += __shfl_xor_sync(0xffffffffu, rs, 2);
            l_s[r] = l_s[r] * alpha + rs;
            #pragma unroll
            for (int nd = 0; nd < 8; nd++) {
                o[nd][2 * r]     *= alpha;
                o[nd][2 * r + 1] *= alpha;
            }
        }

        // O += P @ V  (P fragments straight from S accumulators)
        #pragma unroll
        for (int ks = 0; ks < 4; ks++) {
            const uint32_t a0 = packh2(c[2 * ks][0],     c[2 * ks][1]);
            const uint32_t a1 = packh2(c[2 * ks][2],     c[2 * ks][3]);
            const uint32_t a2 = packh2(c[2 * ks + 1][0], c[2 * ks + 1][1]);
            const uint32_t a3 = packh2(c[2 * ks + 1][2], c[2 * ks + 1][3]);
            const int krow = ks * 16 + 2 * t4;
            #pragma unroll
            for (int nd = 0; nd < 8; nd++) {
                const int d = nd * 8 + gid;
                const uint32_t b0 = packh2(__half2float(Vs[(krow)     * ASLD + d]),
                                           __half2float(Vs[(krow + 1) * ASLD + d]));
                const uint32_t b1 = packh2(__half2float(Vs[(krow + 8) * ASLD + d]),
                                           __half2float(Vs[(krow + 9) * ASLD + d]));
                MMA_F16(o[nd][0], o[nd][1], o[nd][2], o[nd][3], a0, a1, a2, a3, b0, b1);
            }
        }
        __syncthreads();
    }

    // write Y (fp16)
    const float inv0 = 1.0f / l_s[0], inv1 = 1.0f / l_s[1];
    #pragma unroll
    for (int nd = 0; nd < 8; nd++) {
        const int col = nd * 8 + 2 * t4;
        __half2 h0 = __floats2half2_rn(o[nd][0] * inv0, o[nd][1] * inv0);
        __half2 h1 = __floats2half2_rn(o[nd][2] * inv1, o[nd][3] * inv1);
        *reinterpret_cast<__half2*>(Y + rowbase + (size_t)(q0 + wr + gid)     * EDIM + col) = h0;
        *reinterpret_cast<__half2*>(Y + rowbase + (size_t)(q0 + wr + gid + 8) * EDIM + col) = h1;
    }
}

// ---------------- launch ----------------
extern "C" void kernel_launch(void* const* d_in, const int* in_sizes, int n_in,
                              void* d_out, int out_size)
{
    const float* x    = (const float*)d_in[0];
    const float* Wq   = (const float*)d_in[1];
    const float* Wk   = (const float*)d_in[2];
    const float* Wv   = (const float*)d_in[3];
    const float* Wo   = (const float*)d_in[4];
    const float* bo   = (const float*)d_in[5];
    const float* ln1w = (const float*)d_in[6];
    const float* ln2w = (const float*)d_in[7];
    const float* W1   = (const float*)d_in[8];
    const float* b1   = (const float*)d_in[9];
    const float* W2   = (const float*)d_in[10];
    const float* b2   = (const float*)d_in[11];
    float* out = (float*)d_out;

    __half *h, *q, *k, *v, *y, *h2, *ff, *wq, *wk, *wv, *wo, *w1, *w2;
    float *x2;
    cudaGetSymbolAddress((void**)&h,  g_h);
    cudaGetSymbolAddress((void**)&q,  g_q);
    cudaGetSymbolAddress((void**)&k,  g_k);
    cudaGetSymbolAddress((void**)&v,  g_v);
    cudaGetSymbolAddress((void**)&y,  g_y);
    cudaGetSymbolAddress((void**)&x2, g_x2);
    cudaGetSymbolAddress((void**)&h2, g_h2);
    cudaGetSymbolAddress((void**)&ff, g_ff);
    cudaGetSymbolAddress((void**)&wq, g_wq);
    cudaGetSymbolAddress((void**)&wk, g_wk);
    cudaGetSymbolAddress((void**)&wv, g_wv);
    cudaGetSymbolAddress((void**)&wo, g_wo);
    cudaGetSymbolAddress((void**)&w1, g_w1);
    cudaGetSymbolAddress((void**)&w2, g_w2);

    cudaFuncSetAttribute(attn_kernel, cudaFuncAttributeMaxDynamicSharedMemorySize, ATTN_SMEM_BYTES);
    cudaFuncSetAttribute(hgemm<0,0,0,__half>, cudaFuncAttributeMaxDynamicSharedMemorySize, GEMM_SMEM_BYTES);
    cudaFuncSetAttribute(hgemm<1,1,0,float>,  cudaFuncAttributeMaxDynamicSharedMemorySize, GEMM_SMEM_BYTES);
    cudaFuncSetAttribute(hgemm<1,0,1,__half>, cudaFuncAttributeMaxDynamicSharedMemorySize, GEMM_SMEM_BYTES);

    // 0) transpose + fp16 weights [N][K]; fold softmax scale (E^-0.5) into Wq
    dim3 tb(32, 8);
    transpose_half<<<dim3(EDIM/32, EDIM/32), tb>>>(Wq, wq, EDIM, EDIM, 0.03125f);
    transpose_half<<<dim3(EDIM/32, EDIM/32), tb>>>(Wk, wk, EDIM, EDIM, 1.0f);
    transpose_half<<<dim3(EDIM/32, EDIM/32), tb>>>(Wv, wv, EDIM, EDIM, 1.0f);
    transpose_half<<<dim3(EDIM/32, EDIM/32), tb>>>(Wo, wo, EDIM, EDIM, 1.0f);
    transpose_half<<<dim3(FDIM/32, EDIM/32), tb>>>(W1, w1, EDIM, FDIM, 1.0f);
    transpose_half<<<dim3(EDIM/32, FDIM/32), tb>>>(W2, w2, FDIM, EDIM, 1.0f);

    // 1) LN1 (fp16 out)
    ln_kernel<<<BT, 256>>>(x, ln1w, h);

    // 2-4) QKV projections -> fp16
    dim3 gE(EDIM / BN, BT / BM);
    hgemm<0,0,0,__half><<<gE, 256, GEMM_SMEM_BYTES>>>(h, wq, nullptr, nullptr, q, BT, EDIM, EDIM);
    hgemm<0,0,0,__half><<<gE, 256, GEMM_SMEM_BYTES>>>(h, wk, nullptr, nullptr, k, BT, EDIM, EDIM);
    hgemm<0,0,0,__half><<<gE, 256, GEMM_SMEM_BYTES>>>(h, wv, nullptr, nullptr, v, BT, EDIM, EDIM);

    // 5) flash attention (fp16 mma) -> y fp16
    attn_kernel<<<dim3(TSEQ / AQ, NHEAD, BATCH), 256, ATTN_SMEM_BYTES>>>(q, k, v, y);

    // 6) out projection + bias + residual(x) -> x2 fp32
    hgemm<1,1,0,float><<<gE, 256, GEMM_SMEM_BYTES>>>(y, wo, bo, x, x2, BT, EDIM, EDIM);

    // 7) LN2 (fp16 out)
    ln_kernel<<<BT, 256>>>(x2, ln2w, h2);

    // 8) FFN up + relu (fp16 out)
    dim3 gF(FDIM / BN, BT / BM);
    hgemm<1,0,1,__half><<<gF, 256, GEMM_SMEM_BYTES>>>(h2, w1, b1, nullptr, ff, BT, FDIM, EDIM);

    // 9) FFN down + bias + residual(x2) -> out fp32
    hgemm<1,1,0,float><<<gE, 256, GEMM_SMEM_BYTES>>>(ff, w2, b2, x2, out, BT, EDIM, FDIM);
}

// round 8
// speedup vs baseline: 6.3711x; 1.0927x over previous
#include <cuda_runtime.h>
#include <cuda_fp16.h>
#include <cstdint>
#include <math.h>

// Problem constants
#define BATCH 4
#define TSEQ  2048
#define EDIM  1024
#define FDIM  4096
#define NHEAD 16
#define HS    64
#define BT    (BATCH*TSEQ)   // 8192 rows

// single dynamic smem symbol shared by all kernels
extern __shared__ char dyn_smem[];

// ---------------- scratch (no allocation allowed) ----------------
__device__ __half g_h [BT*(size_t)EDIM];   // LN1 out
__device__ __half g_q [BT*(size_t)EDIM];   // Q (fp16, pre-scaled via Wq)
__device__ __half g_k [BT*(size_t)EDIM];
__device__ __half g_v [BT*(size_t)EDIM];
__device__ __half g_y [BT*(size_t)EDIM];   // attention out
__device__ float  g_x2[BT*(size_t)EDIM];
__device__ __half g_h2[BT*(size_t)EDIM];   // LN2 out
__device__ __half g_ff[BT*(size_t)FDIM];   // FFN1 out
// transposed + fp16 weights, [N][K] K-major
__device__ __half g_wq[EDIM*(size_t)EDIM];
__device__ __half g_wk[EDIM*(size_t)EDIM];
__device__ __half g_wv[EDIM*(size_t)EDIM];
__device__ __half g_wo[EDIM*(size_t)EDIM];
__device__ __half g_w1[EDIM*(size_t)FDIM];
__device__ __half g_w2[FDIM*(size_t)EDIM];

// ---------------- helpers ----------------
#define CP_ASYNC16(dst, src) \
    asm volatile("cp.async.cg.shared.global [%0], [%1], 16;\n" :: "r"(dst), "l"(src))
#define CP_COMMIT() asm volatile("cp.async.commit_group;\n" ::)
#define CP_WAIT1()  asm volatile("cp.async.wait_group 1;\n" ::)
#define CP_WAIT0()  asm volatile("cp.async.wait_group 0;\n" ::)

__device__ __forceinline__ uint32_t smem_u32_of(const void* p) {
    uint32_t a;
    asm("{ .reg .u64 t; cvta.to.shared.u64 t, %1; cvt.u32.u64 %0, t; }" : "=r"(a) : "l"(p));
    return a;
}
__device__ __forceinline__ uint32_t packh2(float x, float y) {
    __half2 h = __floats2half2_rn(x, y);
    return *reinterpret_cast<uint32_t*>(&h);
}
#define MMA_F16(c0,c1,c2,c3,a0,a1,a2,a3,b0,b1) \
    asm volatile("mma.sync.aligned.m16n8k16.row.col.f32.f16.f16.f32 " \
        "{%0,%1,%2,%3}, {%4,%5,%6,%7}, {%8,%9}, {%0,%1,%2,%3};\n" \
        : "+f"(c0), "+f"(c1), "+f"(c2), "+f"(c3) \
        : "r"(a0), "r"(a1), "r"(a2), "r"(a3), "r"(b0), "r"(b1))
#define LDSM_X4(r0,r1,r2,r3,addr) \
    asm volatile("ldmatrix.sync.aligned.m8n8.x4.shared.b16 {%0,%1,%2,%3}, [%4];" \
        : "=r"(r0), "=r"(r1), "=r"(r2), "=r"(r3) : "r"(addr))

// ---------------- transpose + fp16 + optional scale: out[N][K] = half(in[K][N]*scale) ----------------
__global__ void __launch_bounds__(256) transpose_half(const float* __restrict__ in,
                                                      __half* __restrict__ out,
                                                      int K, int N, float scale)
{
    __shared__ float t[32][33];
    const int bx = blockIdx.x * 32;  // N offset
    const int by = blockIdx.y * 32;  // K offset
    const int tx = threadIdx.x, ty = threadIdx.y;   // 32 x 8
    #pragma unroll
    for (int i = 0; i < 32; i += 8)
        t[ty + i][tx] = in[(size_t)(by + ty + i) * N + bx + tx];
    __syncthreads();
    #pragma unroll
    for (int i = 0; i < 32; i += 8)
        out[(size_t)(bx + ty + i) * K + by + tx] = __float2half(t[tx][ty + i] * scale);
}

// ---------------- LayerNorm (weight only, eps=1e-5), output fp16 ----------------
__global__ void __launch_bounds__(256) ln_kernel(const float* __restrict__ x,
                                                 const float* __restrict__ w,
                                                 __half* __restrict__ out)
{
    const int row = blockIdx.x;
    const int tid = threadIdx.x;
    const float4 xv = reinterpret_cast<const float4*>(x + (size_t)row * EDIM)[tid];
    float s  = xv.x + xv.y + xv.z + xv.w;
    float s2 = xv.x*xv.x + xv.y*xv.y + xv.z*xv.z + xv.w*xv.w;
    #pragma unroll
    for (int off = 16; off; off >>= 1) {
        s  += __shfl_xor_sync(0xffffffffu, s,  off);
        s2 += __shfl_xor_sync(0xffffffffu, s2, off);
    }
    __shared__ float sh[16];
    const int warp = tid >> 5, lane = tid & 31;
    if (lane == 0) { sh[warp] = s; sh[warp + 8] = s2; }
    __syncthreads();
    s = 0.f; s2 = 0.f;
    #pragma unroll
    for (int i = 0; i < 8; i++) { s += sh[i]; s2 += sh[i + 8]; }
    const float mu  = s * (1.0f / EDIM);
    const float var = s2 * (1.0f / EDIM) - mu * mu;
    const float inv = rsqrtf(var + 1e-5f);
    const float4 wv = reinterpret_cast<const float4*>(w)[tid];
    __half2 o01 = __floats2half2_rn((xv.x - mu) * inv * wv.x, (xv.y - mu) * inv * wv.y);
    __half2 o23 = __floats2half2_rn((xv.z - mu) * inv * wv.z, (xv.w - mu) * inv * wv.w);
    uint2 pk;
    pk.x = *reinterpret_cast<uint32_t*>(&o01);
    pk.y = *reinterpret_cast<uint32_t*>(&o23);
    reinterpret_cast<uint2*>(out + (size_t)row * EDIM)[tid] = pk;
}

// ---------------- fp16 tensor-core GEMM (mma.m16n8k16, ldmatrix, 3-stage) ----------------
// C[M,N] = A[M,K] @ Bt[N,K]^T  (+bias)(+res)(relu)
// Block tile 128x256x64, 3 stages, 256 threads (8 warps 2x4), warp tile 64x64.
#define BM 128
#define BN 256
#define BK 64
#define SLD 72                         // padded stride in halfs (144B rows)
#define A_ST_BYTES (BM*SLD*2)          // 18432
#define B_ST_BYTES (BN*SLD*2)          // 36864
#define STAGE_BYTES (A_ST_BYTES + B_ST_BYTES)  // 55296
#define NSTAGE 3
#define GEMM_SMEM_BYTES (NSTAGE*STAGE_BYTES)   // 165888

__device__ __forceinline__ void store_c2(float* C, size_t idx, float v0, float v1) {
    *reinterpret_cast<float2*>(C + idx) = make_float2(v0, v1);
}
__device__ __forceinline__ void store_c2(__half* C, size_t idx, float v0, float v1) {
    __half2 h = __floats2half2_rn(v0, v1);
    *reinterpret_cast<__half2*>(C + idx) = h;
}

template<int BIAS, int RES, int RELU, typename OutT>
__global__ void __launch_bounds__(256) hgemm(
    const __half* __restrict__ A, const __half* __restrict__ Bt,
    const float* __restrict__ bias, const float* __restrict__ res,
    OutT* __restrict__ C, int M, int N, int K)
{
    const uint32_t smem_u = smem_u32_of(dyn_smem);
    const int tid = threadIdx.x;
    const int warp = tid >> 5, lane = tid & 31;
    const int gid = lane >> 2, t4 = lane & 3;
    const int wm = (warp >> 2) * 64;   // warp row offset (2 warps in M)
    const int wn = (warp & 3) * 64;    // warp col offset (4 warps in N)
    const int m0 = blockIdx.y * BM, n0 = blockIdx.x * BN;

    float c[4][8][4];
    #pragma unroll
    for (int mi = 0; mi < 4; mi++)
        #pragma unroll
        for (int ni = 0; ni < 8; ni++)
            #pragma unroll
            for (int r = 0; r < 4; r++) c[mi][ni][r] = 0.f;

    // ldmatrix per-thread byte offsets (within a stage)
    const uint32_t a_t = (uint32_t)(((lane & 7) + ((lane >> 3) & 1) * 8) * SLD + (lane >> 4) * 8) * 2
                       + (uint32_t)(wm * SLD * 2);
    const uint32_t b_t = (uint32_t)(((lane & 7) + ((lane >> 4) << 3)) * SLD + ((lane >> 3) & 1) * 8) * 2
                       + (uint32_t)(wn * SLD * 2);

    auto load_stage = [&](int t, int buf) {
        const int k0 = t * BK;
        const uint32_t as = smem_u + buf * STAGE_BYTES;
        const uint32_t bs = as + A_ST_BYTES;
        #pragma unroll
        for (int i = 0; i < 4; i++) {       // A: 1024 chunks
            const int ch = tid + i * 256;
            const int row = ch >> 3, kc = ch & 7;
            CP_ASYNC16(as + (uint32_t)(row * (SLD * 2) + kc * 16),
                       A + (size_t)(m0 + row) * K + k0 + kc * 8);
        }
        #pragma unroll
        for (int i = 0; i < 8; i++) {       // B: 2048 chunks
            const int ch = tid + i * 256;
            const int row = ch >> 3, kc = ch & 7;
            CP_ASYNC16(bs + (uint32_t)(row * (SLD * 2) + kc * 16),
                       Bt + (size_t)(n0 + row) * K + k0 + kc * 8);
        }
        CP_COMMIT();
    };

    const int T = K / BK;
    load_stage(0, 0);
    if (T > 1) load_stage(1, 1);
    else       CP_COMMIT();   // keep group count consistent

    for (int t = 0; t < T; t++) {
        const int buf = t % NSTAGE;
        if (t + 1 < T) CP_WAIT1(); else CP_WAIT0();
        __syncthreads();
        if (t + 2 < T) load_stage(t + 2, (t + 2) % NSTAGE);

        const uint32_t abase = smem_u + buf * STAGE_BYTES;
        const uint32_t bbase = abase + A_ST_BYTES;

        #pragma unroll
        for (int ks = 0; ks < 4; ks++) {
            const uint32_t kb2 = (uint32_t)(ks * 16 * 2);
            uint32_t af[4][4];
            #pragma unroll
            for (int mi = 0; mi < 4; mi++)
                LDSM_X4(af[mi][0], af[mi][1], af[mi][2], af[mi][3],
                        abase + a_t + (uint32_t)(mi * 16 * SLD * 2) + kb2);
            #pragma unroll
            for (int p = 0; p < 4; p++) {
                uint32_t b0, b1, b2, b3;
                LDSM_X4(b0, b1, b2, b3,
                        bbase + b_t + (uint32_t)(p * 16 * SLD * 2) + kb2);
                #pragma unroll
                for (int mi = 0; mi < 4; mi++) {
                    MMA_F16(c[mi][2*p][0], c[mi][2*p][1], c[mi][2*p][2], c[mi][2*p][3],
                            af[mi][0], af[mi][1], af[mi][2], af[mi][3], b0, b1);
                    MMA_F16(c[mi][2*p+1][0], c[mi][2*p+1][1], c[mi][2*p+1][2], c[mi][2*p+1][3],
                            af[mi][0], af[mi][1], af[mi][2], af[mi][3], b2, b3);
                }
            }
        }
        __syncthreads();
    }

    // ---- epilogue ----
    #pragma unroll
    for (int mi = 0; mi < 4; mi++) {
        #pragma unroll
        for (int ni = 0; ni < 8; ni++) {
            const int row = m0 + wm + mi * 16 + gid;
            const int col = n0 + wn + ni * 8 + t4 * 2;
            float v0 = c[mi][ni][0], v1 = c[mi][ni][1];
            float v2 = c[mi][ni][2], v3 = c[mi][ni][3];
            if (BIAS) {
                const float2 bv = *reinterpret_cast<const float2*>(bias + col);
                v0 += bv.x; v1 += bv.y; v2 += bv.x; v3 += bv.y;
            }
            if (RES) {
                const float2 r0 = *reinterpret_cast<const float2*>(res + (size_t)row * N + col);
                const float2 r1 = *reinterpret_cast<const float2*>(res + (size_t)(row + 8) * N + col);
                v0 += r0.x; v1 += r0.y; v2 += r1.x; v3 += r1.y;
            }
            if (RELU) {
                v0 = fmaxf(v0, 0.f); v1 = fmaxf(v1, 0.f);
                v2 = fmaxf(v2, 0.f); v3 = fmaxf(v3, 0.f);
            }
            store_c2(C, (size_t)row * N + col, v0, v1);
            store_c2(C, (size_t)(row + 8) * N + col, v2, v3);
        }
    }
}

// ---------------- Flash attention v2, fp16 mma, 128x64 tiles ----------------
#define AQ   128
#define AKV  64
#define ASLD 72
#define QS_OFF   0
#define KV_OFF   (AQ*ASLD)
#define KV_STAGE (AKV*ASLD)
#define ATTN_SMEM_BYTES ((KV_OFF + 4*KV_STAGE)*2)   // 55296

__global__ void __launch_bounds__(256) attn_kernel(
    const __half* __restrict__ Q, const __half* __restrict__ Kg,
    const __half* __restrict__ Vg, __half* __restrict__ Y)
{
    __half* sm = reinterpret_cast<__half*>(dyn_smem);
    const uint32_t smu = smem_u32_of(sm);
    const int tid = threadIdx.x, warp = tid >> 5, lane = tid & 31;
    const int gid = lane >> 2, t4 = lane & 3;
    const int qi = blockIdx.x, h = blockIdx.y, b = blockIdx.z;
    const int q0 = qi * AQ;
    const int wr = warp * 16;
    const size_t rowbase = (size_t)(b * TSEQ) * EDIM + h * HS;

    #pragma unroll
    for (int i = 0; i < 4; i++) {
        const int ch = tid + i * 256;
        const int r = ch >> 3, c8 = ch & 7;
        CP_ASYNC16(smu + (uint32_t)(QS_OFF + r * ASLD + c8 * 8) * 2,
                   Q + rowbase + (size_t)(q0 + r) * EDIM + c8 * 8);
    }
    auto load_kv = [&](int kt, int s) {
        const uint32_t kb = smu + (uint32_t)(KV_OFF + s * 2 * KV_STAGE) * 2;
        const uint32_t vb = kb + KV_STAGE * 2;
        const size_t gk = rowbase + (size_t)(kt * AKV) * EDIM;
        #pragma unroll
        for (int i = 0; i < 2; i++) {
            const int ch = tid + i * 256;
            const int r = ch >> 3, c8 = ch & 7;
            CP_ASYNC16(kb + (uint32_t)(r * ASLD + c8 * 8) * 2, Kg + gk + (size_t)r * EDIM + c8 * 8);
        }
        #pragma unroll
        for (int i = 0; i < 2; i++) {
            const int ch = tid + i * 256;
            const int r = ch >> 3, c8 = ch & 7;
            CP_ASYNC16(vb + (uint32_t)(r * ASLD + c8 * 8) * 2, Vg + gk + (size_t)r * EDIM + c8 * 8);
        }
    };
    load_kv(0, 0);
    CP_COMMIT();

    const int nt = 2 * qi + 2;
    float m_s[2] = {-1e30f, -1e30f}, l_s[2] = {0.f, 0.f};
    float o[8][4];
    #pragma unroll
    for (int i = 0; i < 8; i++)
        #pragma unroll
        for (int j = 0; j < 4; j++) o[i][j] = 0.f;

    for (int kt = 0; kt < nt; kt++) {
        const int buf = kt & 1;
        if (kt + 1 < nt) { load_kv(kt + 1, (kt + 1) & 1); CP_COMMIT(); CP_WAIT1(); }
        else             { CP_WAIT0(); }
        __syncthreads();

        const __half* Qs = sm + QS_OFF;
        const __half* Ks = sm + KV_OFF + buf * 2 * KV_STAGE;
        const __half* Vs = Ks + KV_STAGE;

        float c[8][4];
        #pragma unroll
        for (int i = 0; i < 8; i++)
            #pragma unroll
            for (int j = 0; j < 4; j++) c[i][j] = 0.f;
        #pragma unroll
        for (int ks = 0; ks < 4; ks++) {
            const __half* qp = Qs + (wr + gid) * ASLD + ks * 16 + 2 * t4;
            const uint32_t a0 = *reinterpret_cast<const uint32_t*>(qp);
            const uint32_t a1 = *reinterpret_cast<const uint32_t*>(qp + 8 * ASLD);
            const uint32_t a2 = *reinterpret_cast<const uint32_t*>(qp + 8);
            const uint32_t a3 = *reinterpret_cast<const uint32_t*>(qp + 8 * ASLD + 8);
            #pragma unroll
            for (int ni = 0; ni < 8; ni++) {
                const __half* kp = Ks + (ni * 8 + gid) * ASLD + ks * 16 + 2 * t4;
                const uint32_t b0 = *reinterpret_cast<const uint32_t*>(kp);
                const uint32_t b1 = *reinterpret_cast<const uint32_t*>(kp + 8);
                MMA_F16(c[ni][0], c[ni][1], c[ni][2], c[ni][3], a0, a1, a2, a3, b0, b1);
            }
        }

        if (kt >= 2 * qi) {
            #pragma unroll
            for (int ni = 0; ni < 8; ni++) {
                const int cg = kt * AKV + ni * 8 + 2 * t4;
                const int r0g = q0 + wr + gid, r1g = r0g + 8;
                if (cg     > r0g) c[ni][0] = -1e30f;
                if (cg + 1 > r0g) c[ni][1] = -1e30f;
                if (cg     > r1g) c[ni][2] = -1e30f;
                if (cg + 1 > r1g) c[ni][3] = -1e30f;
            }
        }

        #pragma unroll
        for (int r = 0; r < 2; r++) {
            float mx = -1e30f;
            #pragma unroll
            for (int ni = 0; ni < 8; ni++)
                mx = fmaxf(mx, fmaxf(c[ni][2 * r], c[ni][2 * r + 1]));
            mx = fmaxf(mx, __shfl_xor_sync(0xffffffffu, mx, 1));
            mx = fmaxf(mx, __shfl_xor_sync(0xffffffffu, mx, 2));
            const float m_new = fmaxf(m_s[r], mx);
            const float alpha = __expf(m_s[r] - m_new);
            m_s[r] = m_new;
            float rs = 0.f;
            #pragma unroll
            for (int ni = 0; ni < 8; ni++) {
                const float p0 = __expf(c[ni][2 * r]     - m_new);
                const float p1 = __expf(c[ni][2 * r + 1] - m_new);
                c[ni][2 * r] = p0; c[ni][2 * r + 1] = p1;
                rs += p0 + p1;
            }
            rs += __shfl_xor_sync(0xffffffffu, rs, 1);
            rs += __shfl_xor_sync(0xffffffffu, rs, 2);
            l_s[r] = l_s[r] * alpha + rs;
            #pragma unroll
            for (int nd = 0; nd < 8; nd++) {
                o[nd][2 * r]     *= alpha;
                o[nd][2 * r + 1] *= alpha;
            }
        }

        #pragma unroll
        for (int ks = 0; ks < 4; ks++) {
            const uint32_t a0 = packh2(c[2 * ks][0],     c[2 * ks][1]);
            const uint32_t a1 = packh2(c[2 * ks][2],     c[2 * ks][3]);
            const uint32_t a2 = packh2(c[2 * ks + 1][0], c[2 * ks + 1][1]);
            const uint32_t a3 = packh2(c[2 * ks + 1][2], c[2 * ks + 1][3]);
            const int krow = ks * 16 + 2 * t4;
            #pragma unroll
            for (int nd = 0; nd < 8; nd++) {
                const int d = nd * 8 + gid;
                const uint32_t b0 = packh2(__half2float(Vs[(krow)     * ASLD + d]),
                                           __half2float(Vs[(krow + 1) * ASLD + d]));
                const uint32_t b1 = packh2(__half2float(Vs[(krow + 8) * ASLD + d]),
                                           __half2float(Vs[(krow + 9) * ASLD + d]));
                MMA_F16(o[nd][0], o[nd][1], o[nd][2], o[nd][3], a0, a1, a2, a3, b0, b1);
            }
        }
        __syncthreads();
    }

    const float inv0 = 1.0f / l_s[0], inv1 = 1.0f / l_s[1];
    #pragma unroll
    for (int nd = 0; nd < 8; nd++) {
        const int col = nd * 8 + 2 * t4;
        __half2 h0 = __floats2half2_rn(o[nd][0] * inv0, o[nd][1] * inv0);
        __half2 h1 = __floats2half2_rn(o[nd][2] * inv1, o[nd][3] * inv1);
        *reinterpret_cast<__half2*>(Y + rowbase + (size_t)(q0 + wr + gid)     * EDIM + col) = h0;
        *reinterpret_cast<__half2*>(Y + rowbase + (size_t)(q0 + wr + gid + 8) * EDIM + col) = h1;
    }
}

// ---------------- launch ----------------
extern "C" void kernel_launch(void* const* d_in, const int* in_sizes, int n_in,
                              void* d_out, int out_size)
{
    const float* x    = (const float*)d_in[0];
    const float* Wq   = (const float*)d_in[1];
    const float* Wk   = (const float*)d_in[2];
    const float* Wv   = (const float*)d_in[3];
    const float* Wo   = (const float*)d_in[4];
    const float* bo   = (const float*)d_in[5];
    const float* ln1w = (const float*)d_in[6];
    const float* ln2w = (const float*)d_in[7];
    const float* W1   = (const float*)d_in[8];
    const float* b1   = (const float*)d_in[9];
    const float* W2   = (const float*)d_in[10];
    const float* b2   = (const float*)d_in[11];
    float* out = (float*)d_out;

    __half *h, *q, *k, *v, *y, *h2, *ff, *wq, *wk, *wv, *wo, *w1, *w2;
    float *x2;
    cudaGetSymbolAddress((void**)&h,  g_h);
    cudaGetSymbolAddress((void**)&q,  g_q);
    cudaGetSymbolAddress((void**)&k,  g_k);
    cudaGetSymbolAddress((void**)&v,  g_v);
    cudaGetSymbolAddress((void**)&y,  g_y);
    cudaGetSymbolAddress((void**)&x2, g_x2);
    cudaGetSymbolAddress((void**)&h2, g_h2);
    cudaGetSymbolAddress((void**)&ff, g_ff);
    cudaGetSymbolAddress((void**)&wq, g_wq);
    cudaGetSymbolAddress((void**)&wk, g_wk);
    cudaGetSymbolAddress((void**)&wv, g_wv);
    cudaGetSymbolAddress((void**)&wo, g_wo);
    cudaGetSymbolAddress((void**)&w1, g_w1);
    cudaGetSymbolAddress((void**)&w2, g_w2);

    cudaFuncSetAttribute(attn_kernel, cudaFuncAttributeMaxDynamicSharedMemorySize, ATTN_SMEM_BYTES);
    cudaFuncSetAttribute(hgemm<0,0,0,__half>, cudaFuncAttributeMaxDynamicSharedMemorySize, GEMM_SMEM_BYTES);
    cudaFuncSetAttribute(hgemm<1,1,0,float>,  cudaFuncAttributeMaxDynamicSharedMemorySize, GEMM_SMEM_BYTES);
    cudaFuncSetAttribute(hgemm<1,0,1,__half>, cudaFuncAttributeMaxDynamicSharedMemorySize, GEMM_SMEM_BYTES);

    // 0) transpose + fp16 weights [N][K]; fold softmax scale (E^-0.5) into Wq
    dim3 tb(32, 8);
    transpose_half<<<dim3(EDIM/32, EDIM/32), tb>>>(Wq, wq, EDIM, EDIM, 0.03125f);
    transpose_half<<<dim3(EDIM/32, EDIM/32), tb>>>(Wk, wk, EDIM, EDIM, 1.0f);
    transpose_half<<<dim3(EDIM/32, EDIM/32), tb>>>(Wv, wv, EDIM, EDIM, 1.0f);
    transpose_half<<<dim3(EDIM/32, EDIM/32), tb>>>(Wo, wo, EDIM, EDIM, 1.0f);
    transpose_half<<<dim3(FDIM/32, EDIM/32), tb>>>(W1, w1, EDIM, FDIM, 1.0f);
    transpose_half<<<dim3(EDIM/32, FDIM/32), tb>>>(W2, w2, FDIM, EDIM, 1.0f);

    // 1) LN1 (fp16 out)
    ln_kernel<<<BT, 256>>>(x, ln1w, h);

    // 2-4) QKV projections -> fp16
    dim3 gE(EDIM / BN, BT / BM);
    hgemm<0,0,0,__half><<<gE, 256, GEMM_SMEM_BYTES>>>(h, wq, nullptr, nullptr, q, BT, EDIM, EDIM);
    hgemm<0,0,0,__half><<<gE, 256, GEMM_SMEM_BYTES>>>(h, wk, nullptr, nullptr, k, BT, EDIM, EDIM);
    hgemm<0,0,0,__half><<<gE, 256, GEMM_SMEM_BYTES>>>(h, wv, nullptr, nullptr, v, BT, EDIM, EDIM);

    // 5) flash attention (fp16 mma) -> y fp16
    attn_kernel<<<dim3(TSEQ / AQ, NHEAD, BATCH), 256, ATTN_SMEM_BYTES>>>(q, k, v, y);

    // 6) out projection + bias + residual(x) -> x2 fp32
    hgemm<1,1,0,float><<<gE, 256, GEMM_SMEM_BYTES>>>(y, wo, bo, x, x2, BT, EDIM, EDIM);

    // 7) LN2 (fp16 out)
    ln_kernel<<<BT, 256>>>(x2, ln2w, h2);

    // 8) FFN up + relu (fp16 out)
    dim3 gF(FDIM / BN, BT / BM);
    hgemm<1,0,1,__half><<<gF, 256, GEMM_SMEM_BYTES>>>(h2, w1, b1, nullptr, ff, BT, FDIM, EDIM);

    // 9) FFN down + bias + residual(x2) -> out fp32
    hgemm<1,1,0,float><<<gE, 256, GEMM_SMEM_BYTES>>>(ff, w2, b2, x2, out, BT, EDIM, FDIM);
}